// round 10
// baseline (speedup 1.0000x reference)
#include <cuda_runtime.h>
#include <cuda_bf16.h>
#include <mma.h>
#include <math.h>

using namespace nvcuda;

#define TT 512
#define BB 256
#define IND 256
#define HH 512
#define OUTD 64
#define NBLK 128
#define NTHR 512

// ---------------- device scratch (static allocations only) ----------------
// Stacked split-bf16 weights, per row layout: [hi(512) | lo(512) | hi(512)]
__device__ __nv_bfloat16 g_Wsre[HH*1536];
__device__ __nv_bfloat16 g_Wsim[HH*1536];
__device__ __nv_bfloat16 g_Wstau[HH*1536];
__device__ __nv_bfloat16 g_Us[HH*768];
__device__ __nv_bfloat16 g_Xs[(size_t)TT*BB*512];
// Split-bf16 activations, per row layout: [hi(512) | lo(512)]
__device__ __nv_bfloat16 g_Are[BB*1024];
__device__ __nv_bfloat16 g_Aim[BB*1024];
__device__ __nv_bfloat16 g_Amod[BB*1024];
__device__ float g_zre[BB*HH];
__device__ float g_bias_re[HH];
__device__ float g_bias_im[HH];
__device__ float g_partials[NBLK];
__device__ int bar_cnt;
__device__ volatile unsigned bar_gen;

__device__ __forceinline__ float sigf(float v) { return 1.0f / (1.0f + expf(-v)); }

__device__ __forceinline__ float clampf(float v, float lo, float hi) {
    return fminf(hi, fmaxf(lo, v));
}

// Software grid barrier: all NBLK blocks resident (128 under 148 SMs, 1 CTA/SM).
__device__ __forceinline__ void grid_barrier() {
    __syncthreads();
    if (threadIdx.x == 0) {
        unsigned g = bar_gen;
        __threadfence();
        if (atomicAdd(&bar_cnt, 1) == NBLK - 1) {
            bar_cnt = 0;
            __threadfence();
            bar_gen = g + 1;
        } else {
            while (bar_gen == g) { }
        }
        __threadfence();
    }
    __syncthreads();
}

// Load one chunk tile pair into registers. Threads with isA true load the A
// tile rows, others load the W tile rows. Each thread covers 16 bf16 elems.
__device__ __forceinline__ void load_tiles(
    const __nv_bfloat16* Ag, const __nv_bfloat16* Wgp,
    int RSA, int RSW, int NH, int ch,
    int m0, int n0, bool isA, int lrow, int lcol,
    uint4& r0, uint4& r1)
{
    int ac = (ch < NH) ? ch*128 : (ch - NH)*128;
    int wc = ch*128;
    const __nv_bfloat16* p;
    if (isA) {
        p = Ag + (size_t)(m0 + lrow)*RSA + ac + lcol;
    } else {
        p = Wgp + (size_t)(n0 + lrow)*RSW + wc + lcol;
    }
    r0 = *(const uint4*)(p);
    r1 = *(const uint4*)(p + 8);
}

__device__ __forceinline__ void store_tiles(
    __nv_bfloat16* sAd, __nv_bfloat16* sWd, int buf,
    bool isA, int lrow, int lcol, uint4 r0, uint4 r1)
{
    __nv_bfloat16* dst;
    if (isA) {
        dst = sAd + buf*4352 + lrow*136 + lcol;
    } else {
        dst = sWd + buf*4352 + lrow*136 + lcol;
    }
    *(uint4*)(dst) = r0;
    *(uint4*)(dst + 8) = r1;
}

// Run all chunks of one sub-GEMM, double buffered, prefetching chunk 0 of the
// next sub-GEMM during the last chunk when hasNext is set.
__device__ __forceinline__ void gemm_chunks(
    wmma::fragment<wmma::accumulator, 16, 16, 16, float>& acc,
    const __nv_bfloat16* Ag, const __nv_bfloat16* Wgp,
    int RSA, int RSW, int NH, int NC, int gbase,
    const __nv_bfloat16* nAg, const __nv_bfloat16* nWgp,
    int nRSA, int nRSW, int nNH, int hasNext,
    __nv_bfloat16* sAd, __nv_bfloat16* sWd,
    int m0, int n0, bool isA, int lrow, int lcol,
    int klayer, int mi2, int ni2)
{
    for (int ch = 0; ch < NC; ch++) {
        int cur = (gbase + ch) & 1;
        uint4 r0;
        uint4 r1;
        int doPre = 0;
        if (ch + 1 < NC) {
            load_tiles(Ag, Wgp, RSA, RSW, NH, ch + 1, m0, n0, isA, lrow, lcol, r0, r1);
            doPre = 1;
        } else if (hasNext) {
            load_tiles(nAg, nWgp, nRSA, nRSW, nNH, 0, m0, n0, isA, lrow, lcol, r0, r1);
            doPre = 1;
        }
        const __nv_bfloat16* sAc = sAd + cur*4352;
        const __nv_bfloat16* sWc = sWd + cur*4352;
        #pragma unroll
        for (int ks = 0; ks < 2; ks++) {
            int koff = klayer*32 + ks*16;
            wmma::fragment<wmma::matrix_a, 16, 16, 16, __nv_bfloat16, wmma::row_major> fa;
            wmma::fragment<wmma::matrix_b, 16, 16, 16, __nv_bfloat16, wmma::col_major> fb;
            wmma::load_matrix_sync(fa, sAc + mi2*16*136 + koff, 136);
            wmma::load_matrix_sync(fb, sWc + ni2*16*136 + koff, 136);
            wmma::mma_sync(acc, fa, fb, acc);
        }
        if (doPre) {
            store_tiles(sAd, sWd, (gbase + ch + 1) & 1, isA, lrow, lcol, r0, r1);
            __syncthreads();
        }
    }
}

// Readout for a completed step: y[tprev, 2bx + r, :] from g_zre rows.
__device__ __forceinline__ void do_readout(
    int tprev, int bx, int tid, const float* out_w, float ob,
    float* y, float* zsm, float (*redp)[2][64], int oo, int seg)
{
    if (tid < 256) {
        float4 zv = *(const float4*)(g_zre + (size_t)bx*1024 + tid*4);
        *(float4*)(zsm + tid*4) = zv;
    }
    __syncthreads();
    float a0 = 0.0f;
    float a1 = 0.0f;
    const float4* wrow = (const float4*)(out_w + (size_t)oo*512 + seg*64);
    #pragma unroll 16
    for (int k4 = 0; k4 < 16; k4++) {
        float4 wv = wrow[k4];
        float4 z0 = *(const float4*)(zsm + seg*64 + k4*4);
        float4 z1 = *(const float4*)(zsm + 512 + seg*64 + k4*4);
        a0 += wv.x*z0.x + wv.y*z0.y + wv.z*z0.z + wv.w*z0.w;
        a1 += wv.x*z1.x + wv.y*z1.y + wv.z*z1.z + wv.w*z1.w;
    }
    redp[seg][0][oo] = a0;
    redp[seg][1][oo] = a1;
    __syncthreads();
    if (seg == 0) {
        #pragma unroll
        for (int r = 0; r < 2; r++) {
            float yv = ob;
            #pragma unroll
            for (int s = 0; s < 8; s++) {
                yv += redp[s][r][oo];
            }
            y[((size_t)tprev*BB + bx*2 + r)*OUTD + oo] = yv;
        }
    }
    __syncthreads();
}

__global__ void __launch_bounds__(NTHR, 1)
twistor_persistent(const float* __restrict__ x,
                   const float* __restrict__ W_real_w, const float* __restrict__ W_real_b,
                   const float* __restrict__ W_imag_w, const float* __restrict__ W_imag_b,
                   const float* __restrict__ U_w,      const float* __restrict__ U_b,
                   const float* __restrict__ W_tau_w,  const float* __restrict__ W_tau_b,
                   const float* __restrict__ mask_real,const float* __restrict__ mask_imag,
                   const float* __restrict__ tau_bias,
                   const float* __restrict__ b_real,   const float* __restrict__ b_imag,
                   const float* __restrict__ out_w,    const float* __restrict__ out_b,
                   float* __restrict__ y)
{
    extern __shared__ __align__(16) char dsmem[];
    __nv_bfloat16* sAd = (__nv_bfloat16*)dsmem;     // 2 buffers of 32 x 136
    __nv_bfloat16* sWd = sAd + 8704;                // 2 buffers of 32 x 136
    float* sRedP = (float*)(sWd + 8704);            // 16 layers of 32 x 36

    __shared__ float zsm[1024];
    __shared__ float red[8][2][64];
    __shared__ float rbuf[16];
    __shared__ float warp_s[4];

    int tid = threadIdx.x;
    int bx  = blockIdx.x;
    int gtid = bx*NTHR + tid;
    const int NTOT = NBLK*NTHR;

    // ---------------- prologue ------------------------------------------
    for (int i = gtid; i < HH*HH; i += NTOT) {
        int rr = i >> 9;
        int cc = i & 511;
        int base = rr*1536 + cc;
        float wv;
        float hv;
        __nv_bfloat16 hb;
        __nv_bfloat16 lb;
        wv = W_real_w[i] * sigf(mask_real[i]);
        hb = __float2bfloat16_rn(wv);
        hv = __bfloat162float(hb);
        lb = __float2bfloat16_rn(wv - hv);
        g_Wsre[base] = hb;
        g_Wsre[base+512] = lb;
        g_Wsre[base+1024] = hb;
        wv = W_imag_w[i] * sigf(mask_imag[i]);
        hb = __float2bfloat16_rn(wv);
        hv = __bfloat162float(hb);
        lb = __float2bfloat16_rn(wv - hv);
        g_Wsim[base] = hb;
        g_Wsim[base+512] = lb;
        g_Wsim[base+1024] = hb;
        wv = W_tau_w[i];
        hb = __float2bfloat16_rn(wv);
        hv = __bfloat162float(hb);
        lb = __float2bfloat16_rn(wv - hv);
        g_Wstau[base] = hb;
        g_Wstau[base+512] = lb;
        g_Wstau[base+1024] = hb;
    }
    for (int i = gtid; i < HH*IND; i += NTOT) {
        int rr = i >> 8;
        int cc = i & 255;
        int base = rr*768 + cc;
        float wv = U_w[i];
        __nv_bfloat16 hb = __float2bfloat16_rn(wv);
        float hv = __bfloat162float(hb);
        __nv_bfloat16 lb = __float2bfloat16_rn(wv - hv);
        g_Us[base] = hb;
        g_Us[base+256] = lb;
        g_Us[base+512] = hb;
    }
    for (size_t i = gtid; i < (size_t)TT*BB*IND; i += NTOT) {
        size_t rr = i >> 8;
        int cc = (int)(i & 255);
        float wv = x[i];
        __nv_bfloat16 hb = __float2bfloat16_rn(wv);
        float hv = __bfloat162float(hb);
        __nv_bfloat16 lb = __float2bfloat16_rn(wv - hv);
        g_Xs[rr*512 + cc] = hb;
        g_Xs[rr*512 + 256 + cc] = lb;
    }
    {
        __nv_bfloat16 mh = __float2bfloat16_rn(1e-6f);
        float mhv = __bfloat162float(mh);
        __nv_bfloat16 ml = __float2bfloat16_rn(1e-6f - mhv);
        __nv_bfloat16 zb = __float2bfloat16_rn(0.0f);
        for (int i = gtid; i < BB*HH; i += NTOT) {
            int rr = i >> 9;
            int cc = i & 511;
            g_Are[rr*1024+cc] = zb;
            g_Are[rr*1024+512+cc] = zb;
            g_Aim[rr*1024+cc] = zb;
            g_Aim[rr*1024+512+cc] = zb;
            g_Amod[rr*1024+cc] = mh;
            g_Amod[rr*1024+512+cc] = ml;
        }
    }
    for (int i = gtid; i < HH; i += NTOT) {
        g_bias_re[i] = W_real_b[i] + U_b[i] + b_real[i];
        g_bias_im[i] = W_imag_b[i] + U_b[i] + b_imag[i];
    }
    grid_barrier();

    // ---------------- per-block patch mapping -----------------------------
    int mi = bx >> 4;            // 0..7  : 32-row group over B
    int ni = bx & 15;            // 0..15 : 32-col group over H
    int m0 = mi * 32;
    int n0 = ni * 32;

    bool isA = tid < 256;
    int lp   = tid & 255;
    int lrow = lp >> 3;          // 0..31
    int lcol = (lp & 7) * 16;    // 0,16,...,112

    int wid  = tid >> 5;         // 0..15
    int klayer = wid >> 2;       // 0..3
    int quad = wid & 3;
    int mi2 = quad >> 1;         // 0..1
    int ni2 = quad & 1;          // 0..1

    // B1 and B2 element ownership: two consecutive patch elements per thread
    int e0  = tid * 2;
    int rl  = e0 >> 5;           // patch row 0..31
    int c0  = e0 & 31;           // patch col, even
    int h0  = n0 + c0;

    float2 vbr  = *(const float2*)(&g_bias_re[h0]);
    float2 vbi  = *(const float2*)(&g_bias_im[h0]);
    float2 vwtb = *(const float2*)(&W_tau_b[h0]);
    float2 vtb  = *(const float2*)(&tau_bias[h0]);
    float zre0 = 0.0f;
    float zre1 = 0.0f;
    float zim0 = 0.0f;
    float zim1 = 0.0f;

    int oo  = tid & 63;
    int seg = tid >> 6;
    float ob = out_b[oo];

    for (int t = 0; t < TT; t++) {
        // deferred readout of the previous step
        if (t > 0) {
            do_readout(t - 1, bx, tid, out_w, ob, y, zsm, red, oo, seg);
        }

        // ================= phase A: four sub-GEMMs on one patch ============
        wmma::fragment<wmma::accumulator, 16, 16, 16, float> accRe;
        wmma::fragment<wmma::accumulator, 16, 16, 16, float> accIm;
        wmma::fragment<wmma::accumulator, 16, 16, 16, float> accTa;
        wmma::fragment<wmma::accumulator, 16, 16, 16, float> accUx;
        wmma::fill_fragment(accRe, 0.0f);
        wmma::fill_fragment(accIm, 0.0f);
        wmma::fill_fragment(accTa, 0.0f);
        wmma::fill_fragment(accUx, 0.0f);

        const __nv_bfloat16* xst = g_Xs + (size_t)t*BB*512;

        {
            uint4 p0;
            uint4 p1;
            load_tiles(g_Are, g_Wsre, 1024, 1536, 4, 0, m0, n0, isA, lrow, lcol, p0, p1);
            store_tiles(sAd, sWd, 0, isA, lrow, lcol, p0, p1);
        }
        __syncthreads();

        gemm_chunks(accRe, g_Are, g_Wsre, 1024, 1536, 4, 12, 0,
                    g_Aim, g_Wsim, 1024, 1536, 4, 1,
                    sAd, sWd, m0, n0, isA, lrow, lcol, klayer, mi2, ni2);
        gemm_chunks(accIm, g_Aim, g_Wsim, 1024, 1536, 4, 12, 12,
                    g_Amod, g_Wstau, 1024, 1536, 4, 1,
                    sAd, sWd, m0, n0, isA, lrow, lcol, klayer, mi2, ni2);
        gemm_chunks(accTa, g_Amod, g_Wstau, 1024, 1536, 4, 12, 24,
                    xst, g_Us, 512, 768, 2, 1,
                    sAd, sWd, m0, n0, isA, lrow, lcol, klayer, mi2, ni2);
        gemm_chunks(accUx, xst, g_Us, 512, 768, 2, 6, 36,
                    g_Are, g_Wsre, 1024, 1536, 4, 0,
                    sAd, sWd, m0, n0, isA, lrow, lcol, klayer, mi2, ni2);

        {
            int sOff = klayer*1152 + mi2*576 + ni2*16;
            wmma::store_matrix_sync(sRedP + sOff,        accRe, 36, wmma::mem_row_major);
            wmma::store_matrix_sync(sRedP + 4608 + sOff, accIm, 36, wmma::mem_row_major);
            wmma::store_matrix_sync(sRedP + 9216 + sOff, accTa, 36, wmma::mem_row_major);
            wmma::store_matrix_sync(sRedP + 13824 + sOff, accUx, 36, wmma::mem_row_major);
        }
        __syncthreads();

        // ================= phase B1: reduce layers + elementwise ===========
        float dre[2];
        float dimm[2];
        {
            int rb = rl*36 + c0;
            float gre0 = 0.0f;
            float gre1 = 0.0f;
            float gim0 = 0.0f;
            float gim1 = 0.0f;
            float gta0 = 0.0f;
            float gta1 = 0.0f;
            float gux0 = 0.0f;
            float gux1 = 0.0f;
            #pragma unroll
            for (int l = 0; l < 4; l++) {
                float2 v0 = *(const float2*)(&sRedP[l*1152 + rb]);
                float2 v1 = *(const float2*)(&sRedP[4608 + l*1152 + rb]);
                float2 v2 = *(const float2*)(&sRedP[9216 + l*1152 + rb]);
                float2 v3 = *(const float2*)(&sRedP[13824 + l*1152 + rb]);
                gre0 += v0.x;
                gre1 += v0.y;
                gim0 += v1.x;
                gim1 += v1.y;
                gta0 += v2.x;
                gta1 += v2.y;
                gux0 += v3.x;
                gux1 += v3.y;
            }

            float lsum = 0.0f;
            {
                float dzr = gre0 + gux0 + vbr.x - zre0;
                float dzi = gim0 + gux0 + vbi.x - zim0;
                float tau = clampf(sigf(gta0 + vwtb.x) + vtb.x, 0.01f, 1.0f) + 1e-6f;
                float dr  = clampf(dzr / tau, -10.0f, 10.0f);
                float di  = clampf(dzi / tau, -10.0f, 10.0f);
                lsum += sqrtf(dr*dr + di*di + 1e-12f);
                dre[0] = dr;
                dimm[0] = di;
            }
            {
                float dzr = gre1 + gux1 + vbr.y - zre1;
                float dzi = gim1 + gux1 + vbi.y - zim1;
                float tau = clampf(sigf(gta1 + vwtb.y) + vtb.y, 0.01f, 1.0f) + 1e-6f;
                float dr  = clampf(dzr / tau, -10.0f, 10.0f);
                float di  = clampf(dzi / tau, -10.0f, 10.0f);
                lsum += sqrtf(dr*dr + di*di + 1e-12f);
                dre[1] = dr;
                dimm[1] = di;
            }
            #pragma unroll
            for (int off = 16; off > 0; off >>= 1) {
                lsum += __shfl_down_sync(0xFFFFFFFFu, lsum, off);
            }
            if ((tid & 31) == 0) {
                rbuf[tid >> 5] = lsum;
            }
            __syncthreads();
            if (tid == 0) {
                float s = 0.0f;
                #pragma unroll
                for (int ww = 0; ww < 16; ww++) {
                    s += rbuf[ww];
                }
                g_partials[bx] = s;
            }
        }
        grid_barrier();

        // ================= phase B2: scale + state update ===================
        {
            if (tid < 128) {
                float pv = g_partials[tid];
                #pragma unroll
                for (int off = 16; off > 0; off >>= 1) {
                    pv += __shfl_down_sync(0xFFFFFFFFu, pv, off);
                }
                if ((tid & 31) == 0) {
                    warp_s[tid >> 5] = pv;
                }
            }
            __syncthreads();
            float tot  = ((warp_s[0] + warp_s[1]) + warp_s[2]) + warp_s[3];
            float mean = tot / (float)(BB * HH);
            float scale = 1.0f;
            if (mean > 5.0f) {
                scale = 5.0f / (mean + 1e-6f);
            }

            zre0 = clampf(zre0 + 0.1f * scale * dre[0],  -100.0f, 100.0f);
            zre1 = clampf(zre1 + 0.1f * scale * dre[1],  -100.0f, 100.0f);
            zim0 = clampf(zim0 + 0.1f * scale * dimm[0], -100.0f, 100.0f);
            zim1 = clampf(zim1 + 0.1f * scale * dimm[1], -100.0f, 100.0f);

            float ar0 = tanhf(zre0);
            float ar1 = tanhf(zre1);
            float ai0 = tanhf(zim0);
            float ai1 = tanhf(zim1);
            float am0 = sqrtf(zre0*zre0 + zim0*zim0 + 1e-12f);
            float am1 = sqrtf(zre1*zre1 + zim1*zim1 + 1e-12f);

            int abase = (m0 + rl)*1024 + h0;
            __nv_bfloat162 ph;
            __nv_bfloat162 pl;
            float hv0;
            float hv1;
            ph.x = __float2bfloat16_rn(ar0);
            ph.y = __float2bfloat16_rn(ar1);
            hv0 = __bfloat162float(ph.x);
            hv1 = __bfloat162float(ph.y);
            pl.x = __float2bfloat16_rn(ar0 - hv0);
            pl.y = __float2bfloat16_rn(ar1 - hv1);
            *(__nv_bfloat162*)(&g_Are[abase])     = ph;
            *(__nv_bfloat162*)(&g_Are[abase+512]) = pl;
            ph.x = __float2bfloat16_rn(ai0);
            ph.y = __float2bfloat16_rn(ai1);
            hv0 = __bfloat162float(ph.x);
            hv1 = __bfloat162float(ph.y);
            pl.x = __float2bfloat16_rn(ai0 - hv0);
            pl.y = __float2bfloat16_rn(ai1 - hv1);
            *(__nv_bfloat162*)(&g_Aim[abase])     = ph;
            *(__nv_bfloat162*)(&g_Aim[abase+512]) = pl;
            ph.x = __float2bfloat16_rn(am0);
            ph.y = __float2bfloat16_rn(am1);
            hv0 = __bfloat162float(ph.x);
            hv1 = __bfloat162float(ph.y);
            pl.x = __float2bfloat16_rn(am0 - hv0);
            pl.y = __float2bfloat16_rn(am1 - hv1);
            *(__nv_bfloat162*)(&g_Amod[abase])     = ph;
            *(__nv_bfloat162*)(&g_Amod[abase+512]) = pl;

            float2 vz;
            vz.x = zre0;
            vz.y = zre1;
            *(float2*)(&g_zre[(m0 + rl)*512 + h0]) = vz;
        }
        grid_barrier();
    }

    // final readout for the last step
    do_readout(TT - 1, bx, tid, out_w, ob, y, zsm, red, oo, seg);
}

// ---------------- host launcher (graph-capturable, single node) ------------
extern "C" void kernel_launch(void* const* d_in, const int* in_sizes, int n_in,
                              void* d_out, int out_size)
{
    const float* x         = (const float*)d_in[0];
    const float* W_real_w  = (const float*)d_in[1];
    const float* W_real_b  = (const float*)d_in[2];
    const float* W_imag_w  = (const float*)d_in[3];
    const float* W_imag_b  = (const float*)d_in[4];
    const float* U_w       = (const float*)d_in[5];
    const float* U_b       = (const float*)d_in[6];
    const float* W_tau_w   = (const float*)d_in[7];
    const float* W_tau_b   = (const float*)d_in[8];
    const float* mask_real = (const float*)d_in[9];
    const float* mask_imag = (const float*)d_in[10];
    const float* tau_bias  = (const float*)d_in[11];
    const float* b_real    = (const float*)d_in[12];
    const float* b_imag    = (const float*)d_in[13];
    const float* out_w     = (const float*)d_in[14];
    const float* out_b     = (const float*)d_in[15];
    float* y = (float*)d_out;

    // dynamic smem: A staging + W staging (bf16) + 16 reduction layers (f32)
    int dyn_smem = (8704 + 8704) * 2 + 18432 * 4;
    cudaFuncSetAttribute(twistor_persistent,
                         cudaFuncAttributeMaxDynamicSharedMemorySize, dyn_smem);
    twistor_persistent<<<NBLK, NTHR, dyn_smem>>>(x, W_real_w, W_real_b, W_imag_w, W_imag_b,
                                                 U_w, U_b, W_tau_w, W_tau_b,
                                                 mask_real, mask_imag, tau_bias,
                                                 b_real, b_imag, out_w, out_b, y);
}

// round 12
// speedup vs baseline: 1.1318x; 1.1318x over previous
#include <cuda_runtime.h>
#include <cuda_bf16.h>
#include <mma.h>
#include <math.h>

using namespace nvcuda;

#define TT 512
#define BB 256
#define IND 256
#define HH 512
#define OUTD 64
#define NBLK 128
#define NTHR 512

// ---------------- device scratch (static allocations only) ----------------
// Stacked split-bf16 weights, per row layout: [hi(512) | lo(512) | hi(512)]
__device__ __nv_bfloat16 g_Wsre[HH*1536];
__device__ __nv_bfloat16 g_Wsim[HH*1536];
__device__ __nv_bfloat16 g_Wstau[HH*1536];
__device__ __nv_bfloat16 g_Us[HH*768];
__device__ __nv_bfloat16 g_Xs[(size_t)TT*BB*512];
// Split-bf16 activations, per row layout: [hi(512) | lo(512)]
__device__ __nv_bfloat16 g_Are[BB*1024];
__device__ __nv_bfloat16 g_Aim[BB*1024];
__device__ __nv_bfloat16 g_Amod[BB*1024];
__device__ float g_zre[BB*HH];
__device__ float g_zim[BB*HH];
__device__ float g_gre[BB*HH];
__device__ float g_gim[BB*HH];
__device__ float g_gtau[BB*HH];
__device__ float g_gux[BB*HH];
__device__ float g_bias_re[HH];
__device__ float g_bias_im[HH];
__device__ float g_partials[NBLK];
__device__ int bar_cnt;
__device__ volatile unsigned bar_gen;
// fused scale reduction state (reset each launch in the prologue)
__device__ int g_scnt;
__device__ int g_sflag;
__device__ float g_scale;

__device__ __forceinline__ float sigf(float v) { return 1.0f / (1.0f + expf(-v)); }

__device__ __forceinline__ float clampf(float v, float lo, float hi) {
    return fminf(hi, fmaxf(lo, v));
}

// Atomic-counter grid barrier: all NBLK blocks resident (1 CTA/SM).
__device__ __forceinline__ void grid_barrier() {
    __syncthreads();
    if (threadIdx.x == 0) {
        unsigned g = bar_gen;
        __threadfence();
        if (atomicAdd(&bar_cnt, 1) == NBLK - 1) {
            bar_cnt = 0;
            __threadfence();
            bar_gen = g + 1;
        } else {
            while (bar_gen == g) { }
        }
        __threadfence();
    }
    __syncthreads();
}

__global__ void __launch_bounds__(NTHR, 1)
twistor_persistent(const float* __restrict__ x,
                   const float* __restrict__ W_real_w, const float* __restrict__ W_real_b,
                   const float* __restrict__ W_imag_w, const float* __restrict__ W_imag_b,
                   const float* __restrict__ U_w,      const float* __restrict__ U_b,
                   const float* __restrict__ W_tau_w,  const float* __restrict__ W_tau_b,
                   const float* __restrict__ mask_real,const float* __restrict__ mask_imag,
                   const float* __restrict__ tau_bias,
                   const float* __restrict__ b_real,   const float* __restrict__ b_imag,
                   const float* __restrict__ out_w,    const float* __restrict__ out_b,
                   float* __restrict__ y)
{
    __shared__ __nv_bfloat16 sA[2][64*72];
    __shared__ __nv_bfloat16 sB[2][64*72];
    __shared__ float zsm[2][512];
    __shared__ float red[8][2][64];
    __shared__ float rbuf[16];
    __shared__ float s_scale;

    int tid = threadIdx.x;
    int bx  = blockIdx.x;
    int gtid = bx*NTHR + tid;
    const int NTOT = NBLK*NTHR;

    // ---------------- prologue ------------------------------------------
    if (gtid == 0) {
        g_scnt = 0;
        g_sflag = 0;
    }
    for (int i = gtid; i < HH*HH; i += NTOT) {
        int rr = i >> 9;
        int cc = i & 511;
        int base = rr*1536 + cc;
        float wv;
        float hv;
        __nv_bfloat16 hb;
        __nv_bfloat16 lb;
        wv = W_real_w[i] * sigf(mask_real[i]);
        hb = __float2bfloat16_rn(wv);
        hv = __bfloat162float(hb);
        lb = __float2bfloat16_rn(wv - hv);
        g_Wsre[base] = hb;
        g_Wsre[base+512] = lb;
        g_Wsre[base+1024] = hb;
        wv = W_imag_w[i] * sigf(mask_imag[i]);
        hb = __float2bfloat16_rn(wv);
        hv = __bfloat162float(hb);
        lb = __float2bfloat16_rn(wv - hv);
        g_Wsim[base] = hb;
        g_Wsim[base+512] = lb;
        g_Wsim[base+1024] = hb;
        wv = W_tau_w[i];
        hb = __float2bfloat16_rn(wv);
        hv = __bfloat162float(hb);
        lb = __float2bfloat16_rn(wv - hv);
        g_Wstau[base] = hb;
        g_Wstau[base+512] = lb;
        g_Wstau[base+1024] = hb;
    }
    for (int i = gtid; i < HH*IND; i += NTOT) {
        int rr = i >> 8;
        int cc = i & 255;
        int base = rr*768 + cc;
        float wv = U_w[i];
        __nv_bfloat16 hb = __float2bfloat16_rn(wv);
        float hv = __bfloat162float(hb);
        __nv_bfloat16 lb = __float2bfloat16_rn(wv - hv);
        g_Us[base] = hb;
        g_Us[base+256] = lb;
        g_Us[base+512] = hb;
    }
    for (size_t i = gtid; i < (size_t)TT*BB*IND; i += NTOT) {
        size_t rr = i >> 8;
        int cc = (int)(i & 255);
        float wv = x[i];
        __nv_bfloat16 hb = __float2bfloat16_rn(wv);
        float hv = __bfloat162float(hb);
        __nv_bfloat16 lb = __float2bfloat16_rn(wv - hv);
        g_Xs[rr*512 + cc] = hb;
        g_Xs[rr*512 + 256 + cc] = lb;
    }
    {
        __nv_bfloat16 mh = __float2bfloat16_rn(1e-6f);
        float mhv = __bfloat162float(mh);
        __nv_bfloat16 ml = __float2bfloat16_rn(1e-6f - mhv);
        __nv_bfloat16 zb = __float2bfloat16_rn(0.0f);
        for (int i = gtid; i < BB*HH; i += NTOT) {
            int rr = i >> 9;
            int cc = i & 511;
            g_zre[i] = 0.0f;
            g_zim[i] = 0.0f;
            g_Are[rr*1024+cc] = zb;
            g_Are[rr*1024+512+cc] = zb;
            g_Aim[rr*1024+cc] = zb;
            g_Aim[rr*1024+512+cc] = zb;
            g_Amod[rr*1024+cc] = mh;
            g_Amod[rr*1024+512+cc] = ml;
        }
    }
    for (int i = gtid; i < HH; i += NTOT) {
        g_bias_re[i] = W_real_b[i] + U_b[i] + b_real[i];
        g_bias_im[i] = W_imag_b[i] + U_b[i] + b_imag[i];
    }
    grid_barrier();

    // ---------------- per-block GEMM tile mapping ------------------------
    int which = bx >> 5;
    int tile  = bx & 31;
    int m0    = (tile >> 3) << 6;
    int n0    = (tile & 7)  << 6;

    const __nv_bfloat16* Abase;
    const __nv_bfloat16* Wg;
    float* C;
    int KP;
    int RSA;
    int RSW;
    if (which == 0) {
        Abase = g_Are;  Wg = g_Wsre;  C = g_gre;  KP = 1536; RSA = 1024; RSW = 1536;
    } else if (which == 1) {
        Abase = g_Aim;  Wg = g_Wsim;  C = g_gim;  KP = 1536; RSA = 1024; RSW = 1536;
    } else if (which == 2) {
        Abase = g_Amod; Wg = g_Wstau; C = g_gtau; KP = 1536; RSA = 1024; RSW = 1536;
    } else {
        Abase = g_Xs;   Wg = g_Us;    C = g_gux;  KP = 768;  RSA = 512;  RSW = 768;
    }
    int NC = KP >> 6;

    int lr  = tid >> 3;            // 0..63, one loader row per 8 threads
    int lc8 = (tid & 7) * 8;
    int wid = tid >> 5;            // 0..15
    int wm  = wid & 3;             // 16-row group
    int wn  = wid >> 2;            // 16-col group

    for (int t = 0; t < TT; t++) {
        // ================= phase A: split-bf16 wmma GEMM ===================
        {
            const __nv_bfloat16* Ag = Abase;
            if (which == 3) {
                Ag = g_Xs + (size_t)t*BB*512;
            }

            wmma::fragment<wmma::accumulator, 16, 16, 16, float> acc;
            wmma::fill_fragment(acc, 0.0f);

            // chunk element offsets: A storage wraps, W storage is straight
            // preload chunk 0 into smem buf0, chunk 1 into register slot B
            uint4 raA;
            uint4 rbA;
            uint4 raB;
            uint4 rbB;
            raA = *(const uint4*)(Ag + (size_t)(m0+lr)*RSA + lc8);
            rbA = *(const uint4*)(Wg + (size_t)(n0+lr)*RSW + lc8);
            *(uint4*)(&sA[0][lr*72 + lc8]) = raA;
            *(uint4*)(&sB[0][lr*72 + lc8]) = rbA;
            {
                int kc = 64;
                int ac;
                if (which == 3) {
                    ac = kc & 255;
                } else {
                    ac = kc & 511;
                }
                raB = *(const uint4*)(Ag + (size_t)(m0+lr)*RSA + ac + lc8);
                rbB = *(const uint4*)(Wg + (size_t)(n0+lr)*RSW + kc + lc8);
            }
            __syncthreads();

            for (int ch = 0; ch < NC; ch += 2) {
                // even sub-iteration: compute buf0 holding chunk ch
                if (ch + 2 < NC) {
                    int kc = (ch + 2) << 6;
                    int ac;
                    if (which == 3) {
                        if (kc < 512) { ac = kc & 255; } else { ac = kc - 256; }
                    } else {
                        if (kc < 1024) { ac = kc & 511; } else { ac = kc - 512; }
                    }
                    raA = *(const uint4*)(Ag + (size_t)(m0+lr)*RSA + ac + lc8);
                    rbA = *(const uint4*)(Wg + (size_t)(n0+lr)*RSW + kc + lc8);
                }
                {
                    const __nv_bfloat16* sAc = &sA[0][0];
                    const __nv_bfloat16* sBc = &sB[0][0];
                    #pragma unroll
                    for (int q = 0; q < 4; q++) {
                        wmma::fragment<wmma::matrix_a, 16, 16, 16, __nv_bfloat16, wmma::row_major> fa;
                        wmma::fragment<wmma::matrix_b, 16, 16, 16, __nv_bfloat16, wmma::col_major> fb;
                        wmma::load_matrix_sync(fa, sAc + (wm*16)*72 + q*16, 72);
                        wmma::load_matrix_sync(fb, sBc + (wn*16)*72 + q*16, 72);
                        wmma::mma_sync(acc, fa, fb, acc);
                    }
                }
                // slot B holds chunk ch+1 (always valid: NC is even)
                *(uint4*)(&sA[1][lr*72 + lc8]) = raB;
                *(uint4*)(&sB[1][lr*72 + lc8]) = rbB;
                __syncthreads();

                // odd sub-iteration: compute buf1 holding chunk ch+1
                if (ch + 3 < NC) {
                    int kc = (ch + 3) << 6;
                    int ac;
                    if (which == 3) {
                        if (kc < 512) { ac = kc & 255; } else { ac = kc - 256; }
                    } else {
                        if (kc < 1024) { ac = kc & 511; } else { ac = kc - 512; }
                    }
                    raB = *(const uint4*)(Ag + (size_t)(m0+lr)*RSA + ac + lc8);
                    rbB = *(const uint4*)(Wg + (size_t)(n0+lr)*RSW + kc + lc8);
                }
                {
                    const __nv_bfloat16* sAc = &sA[1][0];
                    const __nv_bfloat16* sBc = &sB[1][0];
                    #pragma unroll
                    for (int q = 0; q < 4; q++) {
                        wmma::fragment<wmma::matrix_a, 16, 16, 16, __nv_bfloat16, wmma::row_major> fa;
                        wmma::fragment<wmma::matrix_b, 16, 16, 16, __nv_bfloat16, wmma::col_major> fb;
                        wmma::load_matrix_sync(fa, sAc + (wm*16)*72 + q*16, 72);
                        wmma::load_matrix_sync(fb, sBc + (wn*16)*72 + q*16, 72);
                        wmma::mma_sync(acc, fa, fb, acc);
                    }
                }
                if (ch + 2 < NC) {
                    // slot A holds chunk ch+2
                    *(uint4*)(&sA[0][lr*72 + lc8]) = raA;
                    *(uint4*)(&sB[0][lr*72 + lc8]) = rbA;
                    __syncthreads();
                }
            }

            float* Cout = C + (size_t)(m0 + wm*16)*512 + n0 + wn*16;
            wmma::store_matrix_sync(Cout, acc, 512, wmma::mem_row_major);
        }
        grid_barrier();

        // ========== phase B: elementwise + fused scale sync + update =======
        float dre[2];
        float dimm[2];
        float zreL[2];
        float zimL[2];
        {
            int i2 = bx * 512 + tid;
            float2 vre = ((const float2*)g_gre)[i2];
            float2 vim = ((const float2*)g_gim)[i2];
            float2 vta = ((const float2*)g_gtau)[i2];
            float2 vux = ((const float2*)g_gux)[i2];
            float2 vzr = ((const float2*)g_zre)[i2];
            float2 vzi = ((const float2*)g_zim)[i2];
            int h0 = (i2 & 255) * 2;
            float2 vbr  = *(const float2*)(&g_bias_re[h0]);
            float2 vbi  = *(const float2*)(&g_bias_im[h0]);
            float2 vwtb = *(const float2*)(&W_tau_b[h0]);
            float2 vtb  = *(const float2*)(&tau_bias[h0]);

            float lsum = 0.0f;
            {
                float dzr = vre.x + vux.x + vbr.x - vzr.x;
                float dzi = vim.x + vux.x + vbi.x - vzi.x;
                float tau = clampf(sigf(vta.x + vwtb.x) + vtb.x, 0.01f, 1.0f) + 1e-6f;
                float dr  = clampf(dzr / tau, -10.0f, 10.0f);
                float di  = clampf(dzi / tau, -10.0f, 10.0f);
                lsum += sqrtf(dr*dr + di*di + 1e-12f);
                dre[0] = dr;
                dimm[0] = di;
                zreL[0] = vzr.x;
                zimL[0] = vzi.x;
            }
            {
                float dzr = vre.y + vux.y + vbr.y - vzr.y;
                float dzi = vim.y + vux.y + vbi.y - vzi.y;
                float tau = clampf(sigf(vta.y + vwtb.y) + vtb.y, 0.01f, 1.0f) + 1e-6f;
                float dr  = clampf(dzr / tau, -10.0f, 10.0f);
                float di  = clampf(dzi / tau, -10.0f, 10.0f);
                lsum += sqrtf(dr*dr + di*di + 1e-12f);
                dre[1] = dr;
                dimm[1] = di;
                zreL[1] = vzr.y;
                zimL[1] = vzi.y;
            }
            #pragma unroll
            for (int off = 16; off > 0; off >>= 1) {
                lsum += __shfl_down_sync(0xFFFFFFFFu, lsum, off);
            }
            if ((tid & 31) == 0) {
                rbuf[tid >> 5] = lsum;
            }
            __syncthreads();
            if (tid == 0) {
                float s = 0.0f;
                #pragma unroll
                for (int ww = 0; ww < 16; ww++) {
                    s += rbuf[ww];
                }
                g_partials[bx] = s;
                __threadfence();
                int old = atomicAdd(&g_scnt, 1);
                if (old == (t + 1) * NBLK - 1) {
                    float tot = 0.0f;
                    for (int b = 0; b < NBLK; b++) {
                        tot += ((volatile float*)g_partials)[b];
                    }
                    float mean = tot / (float)(BB * HH);
                    float sc = 1.0f;
                    if (mean > 5.0f) {
                        sc = 5.0f / (mean + 1e-6f);
                    }
                    g_scale = sc;
                    __threadfence();
                    *((volatile int*)&g_sflag) = t + 1;
                }
                while (*((volatile int*)&g_sflag) < t + 1) { }
                s_scale = *((volatile float*)&g_scale);
            }
            __syncthreads();
        }
        {
            float scale = s_scale;

            int i2 = bx * 512 + tid;
            int flat0 = i2 * 2;
            int arw   = flat0 >> 9;
            int acl   = flat0 & 511;
            int abase = arw*1024 + acl;

            float zrA[2];
            float ziA[2];
            #pragma unroll
            for (int j = 0; j < 2; j++) {
                float znr = clampf(zreL[j] + 0.1f * scale * dre[j],  -100.0f, 100.0f);
                float zni = clampf(zimL[j] + 0.1f * scale * dimm[j], -100.0f, 100.0f);
                zrA[j] = znr;
                ziA[j] = zni;
                float arv = tanhf(znr);
                float aiv = tanhf(zni);
                float amv = sqrtf(znr*znr + zni*zni + 1e-12f);
                __nv_bfloat16 hb;
                float hv;
                hb = __float2bfloat16_rn(arv);
                hv = __bfloat162float(hb);
                g_Are[abase+j] = hb;
                g_Are[abase+512+j] = __float2bfloat16_rn(arv - hv);
                hb = __float2bfloat16_rn(aiv);
                hv = __bfloat162float(hb);
                g_Aim[abase+j] = hb;
                g_Aim[abase+512+j] = __float2bfloat16_rn(aiv - hv);
                hb = __float2bfloat16_rn(amv);
                hv = __bfloat162float(hb);
                g_Amod[abase+j] = hb;
                g_Amod[abase+512+j] = __float2bfloat16_rn(amv - hv);
            }
            float2 vout;
            vout.x = zrA[0];
            vout.y = zrA[1];
            ((float2*)g_zre)[i2] = vout;
            ((float2*)(&zsm[0][0]))[tid] = vout;
            float2 vout2;
            vout2.x = ziA[0];
            vout2.y = ziA[1];
            ((float2*)g_zim)[i2] = vout2;
            __syncthreads();

            // readout: y[t, 2bx + r, :] = zsm[r] times out_w transpose + out_b
            int o   = tid & 63;
            int seg = tid >> 6;     // 0..7, each covers 64 k values
            float acc0 = 0.0f;
            float acc1 = 0.0f;
            const float4* wrow = (const float4*)(out_w + (size_t)o * 512 + seg * 64);
            #pragma unroll 16
            for (int k4 = 0; k4 < 16; k4++) {
                float4 wv = wrow[k4];
                float4 z0 = *(const float4*)(&zsm[0][seg*64 + k4*4]);
                float4 z1 = *(const float4*)(&zsm[1][seg*64 + k4*4]);
                acc0 += wv.x*z0.x + wv.y*z0.y + wv.z*z0.z + wv.w*z0.w;
                acc1 += wv.x*z1.x + wv.y*z1.y + wv.z*z1.z + wv.w*z1.w;
            }
            red[seg][0][o] = acc0;
            red[seg][1][o] = acc1;
            __syncthreads();
            if (seg == 0) {
                float ob = out_b[o];
                #pragma unroll
                for (int r = 0; r < 2; r++) {
                    float yv = ob;
                    #pragma unroll
                    for (int s = 0; s < 8; s++) {
                        yv += red[s][r][o];
                    }
                    y[((size_t)t * BB + bx*2 + r) * OUTD + o] = yv;
                }
            }
        }
        grid_barrier();
    }
}

// ---------------- host launcher (graph-capturable, single node) ------------
extern "C" void kernel_launch(void* const* d_in, const int* in_sizes, int n_in,
                              void* d_out, int out_size)
{
    const float* x         = (const float*)d_in[0];
    const float* W_real_w  = (const float*)d_in[1];
    const float* W_real_b  = (const float*)d_in[2];
    const float* W_imag_w  = (const float*)d_in[3];
    const float* W_imag_b  = (const float*)d_in[4];
    const float* U_w       = (const float*)d_in[5];
    const float* U_b       = (const float*)d_in[6];
    const float* W_tau_w   = (const float*)d_in[7];
    const float* W_tau_b   = (const float*)d_in[8];
    const float* mask_real = (const float*)d_in[9];
    const float* mask_imag = (const float*)d_in[10];
    const float* tau_bias  = (const float*)d_in[11];
    const float* b_real    = (const float*)d_in[12];
    const float* b_imag    = (const float*)d_in[13];
    const float* out_w     = (const float*)d_in[14];
    const float* out_b     = (const float*)d_in[15];
    float* y = (float*)d_out;

    twistor_persistent<<<NBLK, NTHR>>>(x, W_real_w, W_real_b, W_imag_w, W_imag_b,
                                       U_w, U_b, W_tau_w, W_tau_b,
                                       mask_real, mask_imag, tau_bias,
                                       b_real, b_imag, out_w, out_b, y);
}

// round 13
// speedup vs baseline: 1.2752x; 1.1266x over previous
#include <cuda_runtime.h>
#include <cuda_bf16.h>
#include <mma.h>
#include <math.h>

using namespace nvcuda;

#define TT 512
#define BB 256
#define IND 256
#define HH 512
#define OUTD 64
#define NBLK 128
#define NTHR 512
#define WSH 1032
#define WSU 520

// ---------------- device scratch (static allocations only) ----------------
__device__ __nv_bfloat16 g_Xs[(size_t)TT*BB*512];   // per row: [xhi(256) | xlo(256)]
// Split-bf16 activations, per row layout: [hi(512) | lo(512)]
__device__ __nv_bfloat16 g_Are[BB*1024];
__device__ __nv_bfloat16 g_Aim[BB*1024];
__device__ __nv_bfloat16 g_Amod[BB*1024];
__device__ float g_zre[BB*HH];
__device__ float g_zim[BB*HH];
__device__ float g_gre[BB*HH];
__device__ float g_gim[BB*HH];
__device__ float g_gtau[BB*HH];
__device__ float g_gux[BB*HH];
__device__ float g_bias_re[HH];
__device__ float g_bias_im[HH];
__device__ float g_partials[NBLK];
__device__ int bar_cnt;
__device__ volatile unsigned bar_gen;
// fused scale reduction state (reset each launch in the prologue)
__device__ int g_scnt;
__device__ int g_sflag;
__device__ float g_scale;

__device__ __forceinline__ float sigf(float v) { return 1.0f / (1.0f + expf(-v)); }

__device__ __forceinline__ float clampf(float v, float lo, float hi) {
    return fminf(hi, fmaxf(lo, v));
}

// Atomic-counter grid barrier: all NBLK blocks resident (1 CTA/SM).
__device__ __forceinline__ void grid_barrier() {
    __syncthreads();
    if (threadIdx.x == 0) {
        unsigned g = bar_gen;
        __threadfence();
        if (atomicAdd(&bar_cnt, 1) == NBLK - 1) {
            bar_cnt = 0;
            __threadfence();
            bar_gen = g + 1;
        } else {
            while (bar_gen == g) { }
        }
        __threadfence();
    }
    __syncthreads();
}

__global__ void __launch_bounds__(NTHR, 1)
twistor_persistent(const float* __restrict__ x,
                   const float* __restrict__ W_real_w, const float* __restrict__ W_real_b,
                   const float* __restrict__ W_imag_w, const float* __restrict__ W_imag_b,
                   const float* __restrict__ U_w,      const float* __restrict__ U_b,
                   const float* __restrict__ W_tau_w,  const float* __restrict__ W_tau_b,
                   const float* __restrict__ mask_real,const float* __restrict__ mask_imag,
                   const float* __restrict__ tau_bias,
                   const float* __restrict__ b_real,   const float* __restrict__ b_imag,
                   const float* __restrict__ out_w,    const float* __restrict__ out_b,
                   float* __restrict__ y)
{
    extern __shared__ __align__(16) char dsmem[];
    __nv_bfloat16* sW = (__nv_bfloat16*)dsmem;      // 64 rows x WSH (or WSU)
    __nv_bfloat16* sA = sW + 64*WSH;                // 2 buffers of 64 x 72

    __shared__ float zsm[2][512];
    __shared__ float red[8][2][64];
    __shared__ float rbuf[16];
    __shared__ float s_scale;

    int tid = threadIdx.x;
    int bx  = blockIdx.x;
    int gtid = bx*NTHR + tid;
    const int NTOT = NBLK*NTHR;

    // ---------------- per-block GEMM tile mapping ------------------------
    int which = bx >> 5;
    int tile  = bx & 31;
    int m0    = (tile >> 3) << 6;
    int n0    = (tile & 7)  << 6;

    // ---------------- prologue ------------------------------------------
    if (gtid == 0) {
        g_scnt = 0;
        g_sflag = 0;
    }
    // Build this block's weight slice into pinned smem: [Wh | Wl] per row.
    if (which < 3) {
        for (int idx = tid; idx < 64*512; idx += NTHR) {
            int r = idx >> 9;
            int c = idx & 511;
            int grow = n0 + r;
            float wv;
            if (which == 0) {
                wv = W_real_w[grow*512 + c] * sigf(mask_real[grow*512 + c]);
            } else if (which == 1) {
                wv = W_imag_w[grow*512 + c] * sigf(mask_imag[grow*512 + c]);
            } else {
                wv = W_tau_w[grow*512 + c];
            }
            __nv_bfloat16 hb = __float2bfloat16_rn(wv);
            float hv = __bfloat162float(hb);
            __nv_bfloat16 lb = __float2bfloat16_rn(wv - hv);
            sW[r*WSH + c]       = hb;
            sW[r*WSH + 512 + c] = lb;
        }
    } else {
        for (int idx = tid; idx < 64*256; idx += NTHR) {
            int r = idx >> 8;
            int c = idx & 255;
            float wv = U_w[(n0 + r)*256 + c];
            __nv_bfloat16 hb = __float2bfloat16_rn(wv);
            float hv = __bfloat162float(hb);
            __nv_bfloat16 lb = __float2bfloat16_rn(wv - hv);
            sW[r*WSU + c]       = hb;
            sW[r*WSU + 256 + c] = lb;
        }
    }
    for (size_t i = gtid; i < (size_t)TT*BB*IND; i += NTOT) {
        size_t rr = i >> 8;
        int cc = (int)(i & 255);
        float wv = x[i];
        __nv_bfloat16 hb = __float2bfloat16_rn(wv);
        float hv = __bfloat162float(hb);
        __nv_bfloat16 lb = __float2bfloat16_rn(wv - hv);
        g_Xs[rr*512 + cc] = hb;
        g_Xs[rr*512 + 256 + cc] = lb;
    }
    {
        __nv_bfloat16 mh = __float2bfloat16_rn(1e-6f);
        float mhv = __bfloat162float(mh);
        __nv_bfloat16 ml = __float2bfloat16_rn(1e-6f - mhv);
        __nv_bfloat16 zb = __float2bfloat16_rn(0.0f);
        for (int i = gtid; i < BB*HH; i += NTOT) {
            int rr = i >> 9;
            int cc = i & 511;
            g_zre[i] = 0.0f;
            g_zim[i] = 0.0f;
            g_Are[rr*1024+cc] = zb;
            g_Are[rr*1024+512+cc] = zb;
            g_Aim[rr*1024+cc] = zb;
            g_Aim[rr*1024+512+cc] = zb;
            g_Amod[rr*1024+cc] = mh;
            g_Amod[rr*1024+512+cc] = ml;
        }
    }
    for (int i = gtid; i < HH; i += NTOT) {
        g_bias_re[i] = W_real_b[i] + U_b[i] + b_real[i];
        g_bias_im[i] = W_imag_b[i] + U_b[i] + b_imag[i];
    }
    grid_barrier();

    const __nv_bfloat16* Abase;
    float* C;
    int KP;
    int RSA;
    int WS;
    int WWRAP;
    if (which == 0) {
        Abase = g_Are;  C = g_gre;  KP = 1536; RSA = 1024; WS = WSH; WWRAP = 1024;
    } else if (which == 1) {
        Abase = g_Aim;  C = g_gim;  KP = 1536; RSA = 1024; WS = WSH; WWRAP = 1024;
    } else if (which == 2) {
        Abase = g_Amod; C = g_gtau; KP = 1536; RSA = 1024; WS = WSH; WWRAP = 1024;
    } else {
        Abase = g_Xs;   C = g_gux;  KP = 768;  RSA = 512;  WS = WSU; WWRAP = 512;
    }
    int NC = KP >> 6;

    int lr  = tid >> 3;            // 0..63, one loader row per 8 threads
    int lc8 = (tid & 7) * 8;
    int wid = tid >> 5;            // 0..15
    int wm  = wid & 3;             // 16-row group
    int wn  = wid >> 2;            // 16-col group

    for (int t = 0; t < TT; t++) {
        // ================= phase A: split-bf16 wmma GEMM ===================
        {
            const __nv_bfloat16* Ag = Abase;
            if (which == 3) {
                Ag = g_Xs + (size_t)t*BB*512;
            }

            wmma::fragment<wmma::accumulator, 16, 16, 16, float> acc;
            wmma::fill_fragment(acc, 0.0f);

            // preload chunk 0 into smem buf0, chunk 1 into register slot B
            uint4 raA;
            uint4 raB;
            raA = *(const uint4*)(Ag + (size_t)(m0+lr)*RSA + lc8);
            *(uint4*)(&sA[lr*72 + lc8]) = raA;
            {
                int ac;
                if (which == 3) {
                    ac = 64;
                } else {
                    ac = 64;
                }
                raB = *(const uint4*)(Ag + (size_t)(m0+lr)*RSA + ac + lc8);
            }
            __syncthreads();

            for (int ch = 0; ch < NC; ch += 2) {
                // even sub-iteration: compute buf0 holding chunk ch
                if (ch + 2 < NC) {
                    int kc = (ch + 2) << 6;
                    int ac;
                    if (which == 3) {
                        if (kc < 512) { ac = kc & 255; } else { ac = kc - 256; }
                    } else {
                        if (kc < 1024) { ac = kc & 511; } else { ac = kc - 512; }
                    }
                    raA = *(const uint4*)(Ag + (size_t)(m0+lr)*RSA + ac + lc8);
                }
                {
                    int kc = ch << 6;
                    int wOff = (kc < WWRAP) ? kc : (kc - WWRAP);
                    const __nv_bfloat16* sAc = sA;
                    #pragma unroll
                    for (int q = 0; q < 4; q++) {
                        wmma::fragment<wmma::matrix_a, 16, 16, 16, __nv_bfloat16, wmma::row_major> fa;
                        wmma::fragment<wmma::matrix_b, 16, 16, 16, __nv_bfloat16, wmma::col_major> fb;
                        wmma::load_matrix_sync(fa, sAc + (wm*16)*72 + q*16, 72);
                        wmma::load_matrix_sync(fb, sW + (wn*16)*WS + wOff + q*16, WS);
                        wmma::mma_sync(acc, fa, fb, acc);
                    }
                }
                // slot B holds chunk ch+1 (always valid: NC is even)
                __syncthreads();
                *(uint4*)(&sA[4608 + lr*72 + lc8]) = raB;
                __syncthreads();

                // odd sub-iteration: compute buf1 holding chunk ch+1
                if (ch + 3 < NC) {
                    int kc = (ch + 3) << 6;
                    int ac;
                    if (which == 3) {
                        if (kc < 512) { ac = kc & 255; } else { ac = kc - 256; }
                    } else {
                        if (kc < 1024) { ac = kc & 511; } else { ac = kc - 512; }
                    }
                    raB = *(const uint4*)(Ag + (size_t)(m0+lr)*RSA + ac + lc8);
                }
                {
                    int kc = (ch + 1) << 6;
                    int wOff = (kc < WWRAP) ? kc : (kc - WWRAP);
                    const __nv_bfloat16* sAc = sA + 4608;
                    #pragma unroll
                    for (int q = 0; q < 4; q++) {
                        wmma::fragment<wmma::matrix_a, 16, 16, 16, __nv_bfloat16, wmma::row_major> fa;
                        wmma::fragment<wmma::matrix_b, 16, 16, 16, __nv_bfloat16, wmma::col_major> fb;
                        wmma::load_matrix_sync(fa, sAc + (wm*16)*72 + q*16, 72);
                        wmma::load_matrix_sync(fb, sW + (wn*16)*WS + wOff + q*16, WS);
                        wmma::mma_sync(acc, fa, fb, acc);
                    }
                }
                if (ch + 2 < NC) {
                    // slot A holds chunk ch+2
                    __syncthreads();
                    *(uint4*)(&sA[lr*72 + lc8]) = raA;
                    __syncthreads();
                }
            }

            float* Cout = C + (size_t)(m0 + wm*16)*512 + n0 + wn*16;
            wmma::store_matrix_sync(Cout, acc, 512, wmma::mem_row_major);
        }
        grid_barrier();

        // ========== phase B: elementwise + fused scale sync + update =======
        float dre[2];
        float dimm[2];
        float zreL[2];
        float zimL[2];
        {
            int i2 = bx * 512 + tid;
            float2 vre = ((const float2*)g_gre)[i2];
            float2 vim = ((const float2*)g_gim)[i2];
            float2 vta = ((const float2*)g_gtau)[i2];
            float2 vux = ((const float2*)g_gux)[i2];
            float2 vzr = ((const float2*)g_zre)[i2];
            float2 vzi = ((const float2*)g_zim)[i2];
            int h0 = (i2 & 255) * 2;
            float2 vbr  = *(const float2*)(&g_bias_re[h0]);
            float2 vbi  = *(const float2*)(&g_bias_im[h0]);
            float2 vwtb = *(const float2*)(&W_tau_b[h0]);
            float2 vtb  = *(const float2*)(&tau_bias[h0]);

            float lsum = 0.0f;
            {
                float dzr = vre.x + vux.x + vbr.x - vzr.x;
                float dzi = vim.x + vux.x + vbi.x - vzi.x;
                float tau = clampf(sigf(vta.x + vwtb.x) + vtb.x, 0.01f, 1.0f) + 1e-6f;
                float dr  = clampf(dzr / tau, -10.0f, 10.0f);
                float di  = clampf(dzi / tau, -10.0f, 10.0f);
                lsum += sqrtf(dr*dr + di*di + 1e-12f);
                dre[0] = dr;
                dimm[0] = di;
                zreL[0] = vzr.x;
                zimL[0] = vzi.x;
            }
            {
                float dzr = vre.y + vux.y + vbr.y - vzr.y;
                float dzi = vim.y + vux.y + vbi.y - vzi.y;
                float tau = clampf(sigf(vta.y + vwtb.y) + vtb.y, 0.01f, 1.0f) + 1e-6f;
                float dr  = clampf(dzr / tau, -10.0f, 10.0f);
                float di  = clampf(dzi / tau, -10.0f, 10.0f);
                lsum += sqrtf(dr*dr + di*di + 1e-12f);
                dre[1] = dr;
                dimm[1] = di;
                zreL[1] = vzr.y;
                zimL[1] = vzi.y;
            }
            #pragma unroll
            for (int off = 16; off > 0; off >>= 1) {
                lsum += __shfl_down_sync(0xFFFFFFFFu, lsum, off);
            }
            if ((tid & 31) == 0) {
                rbuf[tid >> 5] = lsum;
            }
            __syncthreads();
            if (tid == 0) {
                float s = 0.0f;
                #pragma unroll
                for (int ww = 0; ww < 16; ww++) {
                    s += rbuf[ww];
                }
                g_partials[bx] = s;
                __threadfence();
                int old = atomicAdd(&g_scnt, 1);
                if (old == (t + 1) * NBLK - 1) {
                    float tot = 0.0f;
                    for (int b = 0; b < NBLK; b++) {
                        tot += ((volatile float*)g_partials)[b];
                    }
                    float mean = tot / (float)(BB * HH);
                    float sc = 1.0f;
                    if (mean > 5.0f) {
                        sc = 5.0f / (mean + 1e-6f);
                    }
                    g_scale = sc;
                    __threadfence();
                    *((volatile int*)&g_sflag) = t + 1;
                }
                while (*((volatile int*)&g_sflag) < t + 1) { }
                s_scale = *((volatile float*)&g_scale);
            }
            __syncthreads();
        }
        {
            float scale = s_scale;

            int i2 = bx * 512 + tid;
            int flat0 = i2 * 2;
            int arw   = flat0 >> 9;
            int acl   = flat0 & 511;
            int abase = arw*1024 + acl;

            float zrA[2];
            float ziA[2];
            #pragma unroll
            for (int j = 0; j < 2; j++) {
                float znr = clampf(zreL[j] + 0.1f * scale * dre[j],  -100.0f, 100.0f);
                float zni = clampf(zimL[j] + 0.1f * scale * dimm[j], -100.0f, 100.0f);
                zrA[j] = znr;
                ziA[j] = zni;
                float arv = tanhf(znr);
                float aiv = tanhf(zni);
                float amv = sqrtf(znr*znr + zni*zni + 1e-12f);
                __nv_bfloat16 hb;
                float hv;
                hb = __float2bfloat16_rn(arv);
                hv = __bfloat162float(hb);
                g_Are[abase+j] = hb;
                g_Are[abase+512+j] = __float2bfloat16_rn(arv - hv);
                hb = __float2bfloat16_rn(aiv);
                hv = __bfloat162float(hb);
                g_Aim[abase+j] = hb;
                g_Aim[abase+512+j] = __float2bfloat16_rn(aiv - hv);
                hb = __float2bfloat16_rn(amv);
                hv = __bfloat162float(hb);
                g_Amod[abase+j] = hb;
                g_Amod[abase+512+j] = __float2bfloat16_rn(amv - hv);
            }
            float2 vout;
            vout.x = zrA[0];
            vout.y = zrA[1];
            ((float2*)g_zre)[i2] = vout;
            ((float2*)(&zsm[0][0]))[tid] = vout;
            float2 vout2;
            vout2.x = ziA[0];
            vout2.y = ziA[1];
            ((float2*)g_zim)[i2] = vout2;
            __syncthreads();

            // readout: y[t, 2bx + r, :] = zsm[r] times out_w transpose + out_b
            int o   = tid & 63;
            int seg = tid >> 6;     // 0..7, each covers 64 k values
            float acc0 = 0.0f;
            float acc1 = 0.0f;
            const float4* wrow = (const float4*)(out_w + (size_t)o * 512 + seg * 64);
            #pragma unroll 16
            for (int k4 = 0; k4 < 16; k4++) {
                float4 wv = wrow[k4];
                float4 z0 = *(const float4*)(&zsm[0][seg*64 + k4*4]);
                float4 z1 = *(const float4*)(&zsm[1][seg*64 + k4*4]);
                acc0 += wv.x*z0.x + wv.y*z0.y + wv.z*z0.z + wv.w*z0.w;
                acc1 += wv.x*z1.x + wv.y*z1.y + wv.z*z1.z + wv.w*z1.w;
            }
            red[seg][0][o] = acc0;
            red[seg][1][o] = acc1;
            __syncthreads();
            if (seg == 0) {
                float ob = out_b[o];
                #pragma unroll
                for (int r = 0; r < 2; r++) {
                    float yv = ob;
                    #pragma unroll
                    for (int s = 0; s < 8; s++) {
                        yv += red[s][r][o];
                    }
                    y[((size_t)t * BB + bx*2 + r) * OUTD + o] = yv;
                }
            }
        }
        grid_barrier();
    }
}

// ---------------- host launcher (graph-capturable, single node) ------------
extern "C" void kernel_launch(void* const* d_in, const int* in_sizes, int n_in,
                              void* d_out, int out_size)
{
    const float* x         = (const float*)d_in[0];
    const float* W_real_w  = (const float*)d_in[1];
    const float* W_real_b  = (const float*)d_in[2];
    const float* W_imag_w  = (const float*)d_in[3];
    const float* W_imag_b  = (const float*)d_in[4];
    const float* U_w       = (const float*)d_in[5];
    const float* U_b       = (const float*)d_in[6];
    const float* W_tau_w   = (const float*)d_in[7];
    const float* W_tau_b   = (const float*)d_in[8];
    const float* mask_real = (const float*)d_in[9];
    const float* mask_imag = (const float*)d_in[10];
    const float* tau_bias  = (const float*)d_in[11];
    const float* b_real    = (const float*)d_in[12];
    const float* b_imag    = (const float*)d_in[13];
    const float* out_w     = (const float*)d_in[14];
    const float* out_b     = (const float*)d_in[15];
    float* y = (float*)d_out;

    // dynamic smem: pinned weight slice (64 x WSH bf16) + A double buffer
    int dyn_smem = (64*WSH + 2*64*72) * (int)sizeof(__nv_bfloat16);
    cudaFuncSetAttribute(twistor_persistent,
                         cudaFuncAttributeMaxDynamicSharedMemorySize, dyn_smem);
    twistor_persistent<<<NBLK, NTHR, dyn_smem>>>(x, W_real_w, W_real_b, W_imag_w, W_imag_b,
                                                 U_w, U_b, W_tau_w, W_tau_b,
                                                 mask_real, mask_imag, tau_bias,
                                                 b_real, b_imag, out_w, out_b, y);
}

// round 14
// speedup vs baseline: 1.3618x; 1.0680x over previous
#include <cuda_runtime.h>
#include <cuda_bf16.h>
#include <mma.h>
#include <math.h>

using namespace nvcuda;

#define TT 512
#define BB 256
#define IND 256
#define HH 512
#define OUTD 64
#define NBLK 128
#define NTHR 512
#define WSH 1032
#define WSU 520

// ---------------- device scratch (static allocations only) ----------------
__device__ __nv_bfloat16 g_Xs[(size_t)TT*BB*512];   // per row: [xhi(256) | xlo(256)]
// Split-bf16 activations, per row layout: [hi(512) | lo(512)]
__device__ __nv_bfloat16 g_Are[BB*1024];
__device__ __nv_bfloat16 g_Aim[BB*1024];
__device__ __nv_bfloat16 g_Amod[BB*1024];
__device__ float g_zre[BB*HH];
__device__ float g_zim[BB*HH];
__device__ float g_gre[BB*HH];
__device__ float g_gim[BB*HH];
__device__ float g_gtau[BB*HH];
__device__ float g_gux[BB*HH];
__device__ float g_bias_re[HH];
__device__ float g_bias_im[HH];
__device__ float g_partials[NBLK];
__device__ int bar_cnt;
__device__ volatile unsigned bar_gen;
// fused scale reduction state (reset each launch in the prologue)
__device__ int g_scnt;
__device__ int g_sflag;
__device__ float g_scale;

__device__ __forceinline__ float sigf(float v) { return 1.0f / (1.0f + expf(-v)); }

__device__ __forceinline__ float clampf(float v, float lo, float hi) {
    return fminf(hi, fmaxf(lo, v));
}

// Atomic-counter grid barrier: all NBLK blocks resident (1 CTA/SM).
__device__ __forceinline__ void grid_barrier() {
    __syncthreads();
    if (threadIdx.x == 0) {
        unsigned g = bar_gen;
        __threadfence();
        if (atomicAdd(&bar_cnt, 1) == NBLK - 1) {
            bar_cnt = 0;
            __threadfence();
            bar_gen = g + 1;
        } else {
            while (bar_gen == g) { }
        }
        __threadfence();
    }
    __syncthreads();
}

__global__ void __launch_bounds__(NTHR, 1)
twistor_persistent(const float* __restrict__ x,
                   const float* __restrict__ W_real_w, const float* __restrict__ W_real_b,
                   const float* __restrict__ W_imag_w, const float* __restrict__ W_imag_b,
                   const float* __restrict__ U_w,      const float* __restrict__ U_b,
                   const float* __restrict__ W_tau_w,  const float* __restrict__ W_tau_b,
                   const float* __restrict__ mask_real,const float* __restrict__ mask_imag,
                   const float* __restrict__ tau_bias,
                   const float* __restrict__ b_real,   const float* __restrict__ b_imag,
                   const float* __restrict__ out_w,    const float* __restrict__ out_b,
                   float* __restrict__ y)
{
    extern __shared__ __align__(16) char dsmem[];
    __nv_bfloat16* sW = (__nv_bfloat16*)dsmem;      // 64 rows x WSH (or WSU)
    __nv_bfloat16* sA = sW + 64*WSH;                // 2 buffers of 64 x 72

    __shared__ float zsm[2][512];
    __shared__ float red[8][2][64];
    __shared__ float rbuf[16];
    __shared__ float s_scale;

    int tid = threadIdx.x;
    int bx  = blockIdx.x;
    int gtid = bx*NTHR + tid;
    const int NTOT = NBLK*NTHR;

    // ---------------- per-block GEMM tile mapping ------------------------
    int which = bx >> 5;
    int tile  = bx & 31;
    int m0    = (tile >> 3) << 6;
    int n0    = (tile & 7)  << 6;

    // ---------------- prologue ------------------------------------------
    if (gtid == 0) {
        g_scnt = 0;
        g_sflag = 0;
    }
    // Build this block's weight slice into pinned smem: [Wh | Wl] per row.
    if (which < 3) {
        for (int idx = tid; idx < 64*512; idx += NTHR) {
            int r = idx >> 9;
            int c = idx & 511;
            int grow = n0 + r;
            float wv;
            if (which == 0) {
                wv = W_real_w[grow*512 + c] * sigf(mask_real[grow*512 + c]);
            } else if (which == 1) {
                wv = W_imag_w[grow*512 + c] * sigf(mask_imag[grow*512 + c]);
            } else {
                wv = W_tau_w[grow*512 + c];
            }
            __nv_bfloat16 hb = __float2bfloat16_rn(wv);
            float hv = __bfloat162float(hb);
            __nv_bfloat16 lb = __float2bfloat16_rn(wv - hv);
            sW[r*WSH + c]       = hb;
            sW[r*WSH + 512 + c] = lb;
        }
    } else {
        for (int idx = tid; idx < 64*256; idx += NTHR) {
            int r = idx >> 8;
            int c = idx & 255;
            float wv = U_w[(n0 + r)*256 + c];
            __nv_bfloat16 hb = __float2bfloat16_rn(wv);
            float hv = __bfloat162float(hb);
            __nv_bfloat16 lb = __float2bfloat16_rn(wv - hv);
            sW[r*WSU + c]       = hb;
            sW[r*WSU + 256 + c] = lb;
        }
    }
    for (size_t i = gtid; i < (size_t)TT*BB*IND; i += NTOT) {
        size_t rr = i >> 8;
        int cc = (int)(i & 255);
        float wv = x[i];
        __nv_bfloat16 hb = __float2bfloat16_rn(wv);
        float hv = __bfloat162float(hb);
        __nv_bfloat16 lb = __float2bfloat16_rn(wv - hv);
        g_Xs[rr*512 + cc] = hb;
        g_Xs[rr*512 + 256 + cc] = lb;
    }
    {
        __nv_bfloat16 mh = __float2bfloat16_rn(1e-6f);
        float mhv = __bfloat162float(mh);
        __nv_bfloat16 ml = __float2bfloat16_rn(1e-6f - mhv);
        __nv_bfloat16 zb = __float2bfloat16_rn(0.0f);
        for (int i = gtid; i < BB*HH; i += NTOT) {
            int rr = i >> 9;
            int cc = i & 511;
            g_zre[i] = 0.0f;
            g_zim[i] = 0.0f;
            g_Are[rr*1024+cc] = zb;
            g_Are[rr*1024+512+cc] = zb;
            g_Aim[rr*1024+cc] = zb;
            g_Aim[rr*1024+512+cc] = zb;
            g_Amod[rr*1024+cc] = mh;
            g_Amod[rr*1024+512+cc] = ml;
        }
    }
    for (int i = gtid; i < HH; i += NTOT) {
        g_bias_re[i] = W_real_b[i] + U_b[i] + b_real[i];
        g_bias_im[i] = W_imag_b[i] + U_b[i] + b_imag[i];
    }
    grid_barrier();

    const __nv_bfloat16* Abase;
    float* C;
    int KP;
    int RSA;
    int WS;
    int WWRAP;
    if (which == 0) {
        Abase = g_Are;  C = g_gre;  KP = 1536; RSA = 1024; WS = WSH; WWRAP = 1024;
    } else if (which == 1) {
        Abase = g_Aim;  C = g_gim;  KP = 1536; RSA = 1024; WS = WSH; WWRAP = 1024;
    } else if (which == 2) {
        Abase = g_Amod; C = g_gtau; KP = 1536; RSA = 1024; WS = WSH; WWRAP = 1024;
    } else {
        Abase = g_Xs;   C = g_gux;  KP = 768;  RSA = 512;  WS = WSU; WWRAP = 512;
    }
    int NC = KP >> 6;

    int lr  = tid >> 3;            // 0..63, one loader row per 8 threads
    int lc8 = (tid & 7) * 8;
    int wid = tid >> 5;            // 0..15
    int wm  = wid & 3;             // 16-row group
    int wn  = wid >> 2;            // 16-col group

    int oo  = tid & 63;
    int seg = tid >> 6;
    float ob = out_b[oo];

    for (int t = 0; t < TT; t++) {
        // ================= phase A: split-bf16 wmma GEMM ===================
        {
            const __nv_bfloat16* Ag = Abase;
            if (which == 3) {
                Ag = g_Xs + (size_t)t*BB*512;
            }

            wmma::fragment<wmma::accumulator, 16, 16, 16, float> acc;
            wmma::fill_fragment(acc, 0.0f);

            // preload chunk 0 into smem buf0, chunk 1 into register slot B
            uint4 raA;
            uint4 raB;
            raA = *(const uint4*)(Ag + (size_t)(m0+lr)*RSA + lc8);
            *(uint4*)(&sA[lr*72 + lc8]) = raA;
            raB = *(const uint4*)(Ag + (size_t)(m0+lr)*RSA + 64 + lc8);
            __syncthreads();

            for (int ch = 0; ch < NC; ch += 2) {
                // even sub-iteration: compute buf0 holding chunk ch
                if (ch + 2 < NC) {
                    int kc = (ch + 2) << 6;
                    int ac;
                    if (which == 3) {
                        if (kc < 512) { ac = kc & 255; } else { ac = kc - 256; }
                    } else {
                        if (kc < 1024) { ac = kc & 511; } else { ac = kc - 512; }
                    }
                    raA = *(const uint4*)(Ag + (size_t)(m0+lr)*RSA + ac + lc8);
                }
                {
                    int kc = ch << 6;
                    int wOff = (kc < WWRAP) ? kc : (kc - WWRAP);
                    const __nv_bfloat16* sAc = sA;
                    #pragma unroll
                    for (int q = 0; q < 4; q++) {
                        wmma::fragment<wmma::matrix_a, 16, 16, 16, __nv_bfloat16, wmma::row_major> fa;
                        wmma::fragment<wmma::matrix_b, 16, 16, 16, __nv_bfloat16, wmma::col_major> fb;
                        wmma::load_matrix_sync(fa, sAc + (wm*16)*72 + q*16, 72);
                        wmma::load_matrix_sync(fb, sW + (wn*16)*WS + wOff + q*16, WS);
                        wmma::mma_sync(acc, fa, fb, acc);
                    }
                }
                // slot B holds chunk ch+1 (always valid: NC is even)
                *(uint4*)(&sA[4608 + lr*72 + lc8]) = raB;
                __syncthreads();

                // odd sub-iteration: compute buf1 holding chunk ch+1
                if (ch + 3 < NC) {
                    int kc = (ch + 3) << 6;
                    int ac;
                    if (which == 3) {
                        if (kc < 512) { ac = kc & 255; } else { ac = kc - 256; }
                    } else {
                        if (kc < 1024) { ac = kc & 511; } else { ac = kc - 512; }
                    }
                    raB = *(const uint4*)(Ag + (size_t)(m0+lr)*RSA + ac + lc8);
                }
                {
                    int kc = (ch + 1) << 6;
                    int wOff = (kc < WWRAP) ? kc : (kc - WWRAP);
                    const __nv_bfloat16* sAc = sA + 4608;
                    #pragma unroll
                    for (int q = 0; q < 4; q++) {
                        wmma::fragment<wmma::matrix_a, 16, 16, 16, __nv_bfloat16, wmma::row_major> fa;
                        wmma::fragment<wmma::matrix_b, 16, 16, 16, __nv_bfloat16, wmma::col_major> fb;
                        wmma::load_matrix_sync(fa, sAc + (wm*16)*72 + q*16, 72);
                        wmma::load_matrix_sync(fb, sW + (wn*16)*WS + wOff + q*16, WS);
                        wmma::mma_sync(acc, fa, fb, acc);
                    }
                }
                if (ch + 2 < NC) {
                    // slot A holds chunk ch+2
                    *(uint4*)(&sA[lr*72 + lc8]) = raA;
                    __syncthreads();
                }
            }

            float* Cout = C + (size_t)(m0 + wm*16)*512 + n0 + wn*16;
            wmma::store_matrix_sync(Cout, acc, 512, wmma::mem_row_major);
        }

        // ===== deferred readout of step t-1, done by the idle Ux blocks =====
        if (which == 3 && t > 0) {
            int bxu = tile;                  // 0..31 -> B rows [8*bxu, 8*bxu+8)
            float* zst  = (float*)(sW + 64*WSU);   // 8 x 512 floats
            float* redU = zst + 4096;              // seg x row x 64 floats
            __syncthreads();
            const float4* zsrc = (const float4*)(g_zre + (size_t)bxu*8*512);
            for (int i = tid; i < 1024; i += NTHR) {
                ((float4*)zst)[i] = zsrc[i];
            }
            __syncthreads();
            float acc0;
            float acc1;
            float acc2;
            float acc3;
            float acc4;
            float acc5;
            float acc6;
            float acc7;
            acc0 = 0.0f; acc1 = 0.0f; acc2 = 0.0f; acc3 = 0.0f;
            acc4 = 0.0f; acc5 = 0.0f; acc6 = 0.0f; acc7 = 0.0f;
            const float4* wrow = (const float4*)(out_w + (size_t)oo*512 + seg*64);
            #pragma unroll 8
            for (int k4 = 0; k4 < 16; k4++) {
                float4 wv = wrow[k4];
                int zb = seg*64 + k4*4;
                float4 z0 = *(const float4*)(zst + 0*512 + zb);
                float4 z1 = *(const float4*)(zst + 1*512 + zb);
                float4 z2 = *(const float4*)(zst + 2*512 + zb);
                float4 z3 = *(const float4*)(zst + 3*512 + zb);
                acc0 += wv.x*z0.x + wv.y*z0.y + wv.z*z0.z + wv.w*z0.w;
                acc1 += wv.x*z1.x + wv.y*z1.y + wv.z*z1.z + wv.w*z1.w;
                acc2 += wv.x*z2.x + wv.y*z2.y + wv.z*z2.z + wv.w*z2.w;
                acc3 += wv.x*z3.x + wv.y*z3.y + wv.z*z3.z + wv.w*z3.w;
                float4 z4 = *(const float4*)(zst + 4*512 + zb);
                float4 z5 = *(const float4*)(zst + 5*512 + zb);
                float4 z6 = *(const float4*)(zst + 6*512 + zb);
                float4 z7 = *(const float4*)(zst + 7*512 + zb);
                acc4 += wv.x*z4.x + wv.y*z4.y + wv.z*z4.z + wv.w*z4.w;
                acc5 += wv.x*z5.x + wv.y*z5.y + wv.z*z5.z + wv.w*z5.w;
                acc6 += wv.x*z6.x + wv.y*z6.y + wv.z*z6.z + wv.w*z6.w;
                acc7 += wv.x*z7.x + wv.y*z7.y + wv.z*z7.z + wv.w*z7.w;
            }
            redU[(seg*8 + 0)*64 + oo] = acc0;
            redU[(seg*8 + 1)*64 + oo] = acc1;
            redU[(seg*8 + 2)*64 + oo] = acc2;
            redU[(seg*8 + 3)*64 + oo] = acc3;
            redU[(seg*8 + 4)*64 + oo] = acc4;
            redU[(seg*8 + 5)*64 + oo] = acc5;
            redU[(seg*8 + 6)*64 + oo] = acc6;
            redU[(seg*8 + 7)*64 + oo] = acc7;
            __syncthreads();
            if (seg == 0) {
                #pragma unroll
                for (int r = 0; r < 8; r++) {
                    float yv = ob;
                    #pragma unroll
                    for (int s = 0; s < 8; s++) {
                        yv += redU[(s*8 + r)*64 + oo];
                    }
                    y[((size_t)(t-1)*BB + bxu*8 + r)*OUTD + oo] = yv;
                }
            }
        }
        grid_barrier();

        // ========== phase B: elementwise + fused scale sync + update =======
        float dre[2];
        float dimm[2];
        float zreL[2];
        float zimL[2];
        {
            int i2 = bx * 512 + tid;
            float2 vre = ((const float2*)g_gre)[i2];
            float2 vim = ((const float2*)g_gim)[i2];
            float2 vta = ((const float2*)g_gtau)[i2];
            float2 vux = ((const float2*)g_gux)[i2];
            float2 vzr = ((const float2*)g_zre)[i2];
            float2 vzi = ((const float2*)g_zim)[i2];
            int h0 = (i2 & 255) * 2;
            float2 vbr  = *(const float2*)(&g_bias_re[h0]);
            float2 vbi  = *(const float2*)(&g_bias_im[h0]);
            float2 vwtb = *(const float2*)(&W_tau_b[h0]);
            float2 vtb  = *(const float2*)(&tau_bias[h0]);

            float lsum = 0.0f;
            {
                float dzr = vre.x + vux.x + vbr.x - vzr.x;
                float dzi = vim.x + vux.x + vbi.x - vzi.x;
                float tau = clampf(sigf(vta.x + vwtb.x) + vtb.x, 0.01f, 1.0f) + 1e-6f;
                float dr  = clampf(dzr / tau, -10.0f, 10.0f);
                float di  = clampf(dzi / tau, -10.0f, 10.0f);
                lsum += sqrtf(dr*dr + di*di + 1e-12f);
                dre[0] = dr;
                dimm[0] = di;
                zreL[0] = vzr.x;
                zimL[0] = vzi.x;
            }
            {
                float dzr = vre.y + vux.y + vbr.y - vzr.y;
                float dzi = vim.y + vux.y + vbi.y - vzi.y;
                float tau = clampf(sigf(vta.y + vwtb.y) + vtb.y, 0.01f, 1.0f) + 1e-6f;
                float dr  = clampf(dzr / tau, -10.0f, 10.0f);
                float di  = clampf(dzi / tau, -10.0f, 10.0f);
                lsum += sqrtf(dr*dr + di*di + 1e-12f);
                dre[1] = dr;
                dimm[1] = di;
                zreL[1] = vzr.y;
                zimL[1] = vzi.y;
            }
            #pragma unroll
            for (int off = 16; off > 0; off >>= 1) {
                lsum += __shfl_down_sync(0xFFFFFFFFu, lsum, off);
            }
            if ((tid & 31) == 0) {
                rbuf[tid >> 5] = lsum;
            }
            __syncthreads();
            if (tid == 0) {
                float s = 0.0f;
                #pragma unroll
                for (int ww = 0; ww < 16; ww++) {
                    s += rbuf[ww];
                }
                g_partials[bx] = s;
                __threadfence();
                int old = atomicAdd(&g_scnt, 1);
                if (old == (t + 1) * NBLK - 1) {
                    float tot = 0.0f;
                    for (int b = 0; b < NBLK; b++) {
                        tot += ((volatile float*)g_partials)[b];
                    }
                    float mean = tot / (float)(BB * HH);
                    float sc = 1.0f;
                    if (mean > 5.0f) {
                        sc = 5.0f / (mean + 1e-6f);
                    }
                    g_scale = sc;
                    __threadfence();
                    *((volatile int*)&g_sflag) = t + 1;
                }
                while (*((volatile int*)&g_sflag) < t + 1) { }
                s_scale = *((volatile float*)&g_scale);
            }
            __syncthreads();
        }
        {
            float scale = s_scale;

            int i2 = bx * 512 + tid;
            int flat0 = i2 * 2;
            int arw   = flat0 >> 9;
            int acl   = flat0 & 511;
            int abase = arw*1024 + acl;

            float zrA[2];
            float ziA[2];
            #pragma unroll
            for (int j = 0; j < 2; j++) {
                float znr = clampf(zreL[j] + 0.1f * scale * dre[j],  -100.0f, 100.0f);
                float zni = clampf(zimL[j] + 0.1f * scale * dimm[j], -100.0f, 100.0f);
                zrA[j] = znr;
                ziA[j] = zni;
                float arv = tanhf(znr);
                float aiv = tanhf(zni);
                float amv = sqrtf(znr*znr + zni*zni + 1e-12f);
                __nv_bfloat16 hb;
                float hv;
                hb = __float2bfloat16_rn(arv);
                hv = __bfloat162float(hb);
                g_Are[abase+j] = hb;
                g_Are[abase+512+j] = __float2bfloat16_rn(arv - hv);
                hb = __float2bfloat16_rn(aiv);
                hv = __bfloat162float(hb);
                g_Aim[abase+j] = hb;
                g_Aim[abase+512+j] = __float2bfloat16_rn(aiv - hv);
                hb = __float2bfloat16_rn(amv);
                hv = __bfloat162float(hb);
                g_Amod[abase+j] = hb;
                g_Amod[abase+512+j] = __float2bfloat16_rn(amv - hv);
            }
            float2 vout;
            vout.x = zrA[0];
            vout.y = zrA[1];
            ((float2*)g_zre)[i2] = vout;
            float2 vout2;
            vout2.x = ziA[0];
            vout2.y = ziA[1];
            ((float2*)g_zim)[i2] = vout2;
        }
        grid_barrier();
    }

    // ---------------- epilogue: readout of the final step ------------------
    {
        float* zst2 = &zsm[0][0];
        const float4* zsrc = (const float4*)(g_zre + (size_t)bx*1024);
        for (int i = tid; i < 256; i += NTHR) {
            ((float4*)zst2)[i] = zsrc[i];
        }
        __syncthreads();
        float acc0 = 0.0f;
        float acc1 = 0.0f;
        const float4* wrow = (const float4*)(out_w + (size_t)oo*512 + seg*64);
        #pragma unroll 16
        for (int k4 = 0; k4 < 16; k4++) {
            float4 wv = wrow[k4];
            float4 z0 = *(const float4*)(zst2 + seg*64 + k4*4);
            float4 z1 = *(const float4*)(zst2 + 512 + seg*64 + k4*4);
            acc0 += wv.x*z0.x + wv.y*z0.y + wv.z*z0.z + wv.w*z0.w;
            acc1 += wv.x*z1.x + wv.y*z1.y + wv.z*z1.z + wv.w*z1.w;
        }
        red[seg][0][oo] = acc0;
        red[seg][1][oo] = acc1;
        __syncthreads();
        if (seg == 0) {
            #pragma unroll
            for (int r = 0; r < 2; r++) {
                float yv = ob;
                #pragma unroll
                for (int s = 0; s < 8; s++) {
                    yv += red[s][r][oo];
                }
                y[((size_t)(TT-1)*BB + bx*2 + r)*OUTD + oo] = yv;
            }
        }
    }
}

// ---------------- host launcher (graph-capturable, single node) ------------
extern "C" void kernel_launch(void* const* d_in, const int* in_sizes, int n_in,
                              void* d_out, int out_size)
{
    const float* x         = (const float*)d_in[0];
    const float* W_real_w  = (const float*)d_in[1];
    const float* W_real_b  = (const float*)d_in[2];
    const float* W_imag_w  = (const float*)d_in[3];
    const float* W_imag_b  = (const float*)d_in[4];
    const float* U_w       = (const float*)d_in[5];
    const float* U_b       = (const float*)d_in[6];
    const float* W_tau_w   = (const float*)d_in[7];
    const float* W_tau_b   = (const float*)d_in[8];
    const float* mask_real = (const float*)d_in[9];
    const float* mask_imag = (const float*)d_in[10];
    const float* tau_bias  = (const float*)d_in[11];
    const float* b_real    = (const float*)d_in[12];
    const float* b_imag    = (const float*)d_in[13];
    const float* out_w     = (const float*)d_in[14];
    const float* out_b     = (const float*)d_in[15];
    float* y = (float*)d_out;

    // dynamic smem: pinned weight slice (64 x WSH bf16) + A double buffer
    int dyn_smem = (64*WSH + 2*64*72) * (int)sizeof(__nv_bfloat16);
    cudaFuncSetAttribute(twistor_persistent,
                         cudaFuncAttributeMaxDynamicSharedMemorySize, dyn_smem);
    twistor_persistent<<<NBLK, NTHR, dyn_smem>>>(x, W_real_w, W_real_b, W_imag_w, W_imag_b,
                                                 U_w, U_b, W_tau_w, W_tau_b,
                                                 mask_real, mask_imag, tau_bias,
                                                 b_real, b_imag, out_w, out_b, y);
}

// round 16
// speedup vs baseline: 1.4632x; 1.0744x over previous
#include <cuda_runtime.h>
#include <cuda_bf16.h>
#include <mma.h>
#include <math.h>

using namespace nvcuda;

#define TT 512
#define BB 256
#define IND 256
#define HH 512
#define OUTD 64
#define NBLK 128
#define NTHR 512
#define WSH 1032
#define WSU 520
#define ASTR 136

// ---------------- device scratch (static allocations only) ----------------
__device__ __nv_bfloat16 g_Xs[(size_t)TT*BB*512];   // per row: [xhi(256) | xlo(256)]
// Split-bf16 activations, per row layout: [hi(512) | lo(512)]
__device__ __nv_bfloat16 g_Are[BB*1024];
__device__ __nv_bfloat16 g_Aim[BB*1024];
__device__ __nv_bfloat16 g_Amod[BB*1024];
__device__ float g_zre[BB*HH];
__device__ float g_zim[BB*HH];
__device__ float g_gre[BB*HH];
__device__ float g_gim[BB*HH];
__device__ float g_gtau[BB*HH];
__device__ float g_gux[BB*HH];
__device__ float g_bias_re[HH];
__device__ float g_bias_im[HH];
__device__ float g_partials[NBLK];
__device__ int bar_cnt;
__device__ volatile unsigned bar_gen;
// fused scale reduction state (reset each launch in the prologue)
__device__ int g_scnt;
__device__ int g_sflag;
__device__ float g_scale;

__device__ __forceinline__ float sigf(float v) { return 1.0f / (1.0f + expf(-v)); }

__device__ __forceinline__ float clampf(float v, float lo, float hi) {
    return fminf(hi, fmaxf(lo, v));
}

// Atomic-counter grid barrier: all NBLK blocks resident (1 CTA/SM).
__device__ __forceinline__ void grid_barrier() {
    __syncthreads();
    if (threadIdx.x == 0) {
        unsigned g = bar_gen;
        __threadfence();
        if (atomicAdd(&bar_cnt, 1) == NBLK - 1) {
            bar_cnt = 0;
            __threadfence();
            bar_gen = g + 1;
        } else {
            while (bar_gen == g) { }
        }
        __threadfence();
    }
    __syncthreads();
}

__global__ void __launch_bounds__(NTHR, 1)
twistor_persistent(const float* __restrict__ x,
                   const float* __restrict__ W_real_w, const float* __restrict__ W_real_b,
                   const float* __restrict__ W_imag_w, const float* __restrict__ W_imag_b,
                   const float* __restrict__ U_w,      const float* __restrict__ U_b,
                   const float* __restrict__ W_tau_w,  const float* __restrict__ W_tau_b,
                   const float* __restrict__ mask_real,const float* __restrict__ mask_imag,
                   const float* __restrict__ tau_bias,
                   const float* __restrict__ b_real,   const float* __restrict__ b_imag,
                   const float* __restrict__ out_w,    const float* __restrict__ out_b,
                   float* __restrict__ y)
{
    extern __shared__ __align__(16) char dsmem[];
    __nv_bfloat16* sW = (__nv_bfloat16*)dsmem;      // 64 rows x WSH (or WSU)
    __nv_bfloat16* sA = sW + 64*WSH;                // 2 buffers of 64 x ASTR

    __shared__ float zsm[2][512];
    __shared__ float red[8][2][64];
    __shared__ float rbuf[16];
    __shared__ float s_scale;

    int tid = threadIdx.x;
    int bx  = blockIdx.x;
    int gtid = bx*NTHR + tid;
    const int NTOT = NBLK*NTHR;

    // ---------------- per-block GEMM tile mapping ------------------------
    int which = bx >> 5;
    int tile  = bx & 31;
    int m0    = (tile >> 3) << 6;
    int n0    = (tile & 7)  << 6;

    // ---------------- prologue ------------------------------------------
    if (gtid == 0) {
        g_scnt = 0;
        g_sflag = 0;
    }
    // Build this block's weight slice into pinned smem: [Wh | Wl] per row.
    if (which < 3) {
        for (int idx = tid; idx < 64*512; idx += NTHR) {
            int r = idx >> 9;
            int c = idx & 511;
            int grow = n0 + r;
            float wv;
            if (which == 0) {
                wv = W_real_w[grow*512 + c] * sigf(mask_real[grow*512 + c]);
            } else if (which == 1) {
                wv = W_imag_w[grow*512 + c] * sigf(mask_imag[grow*512 + c]);
            } else {
                wv = W_tau_w[grow*512 + c];
            }
            __nv_bfloat16 hb = __float2bfloat16_rn(wv);
            float hv = __bfloat162float(hb);
            __nv_bfloat16 lb = __float2bfloat16_rn(wv - hv);
            sW[r*WSH + c]       = hb;
            sW[r*WSH + 512 + c] = lb;
        }
    } else {
        for (int idx = tid; idx < 64*256; idx += NTHR) {
            int r = idx >> 8;
            int c = idx & 255;
            float wv = U_w[(n0 + r)*256 + c];
            __nv_bfloat16 hb = __float2bfloat16_rn(wv);
            float hv = __bfloat162float(hb);
            __nv_bfloat16 lb = __float2bfloat16_rn(wv - hv);
            sW[r*WSU + c]       = hb;
            sW[r*WSU + 256 + c] = lb;
        }
    }
    for (size_t i = gtid; i < (size_t)TT*BB*IND; i += NTOT) {
        size_t rr = i >> 8;
        int cc = (int)(i & 255);
        float wv = x[i];
        __nv_bfloat16 hb = __float2bfloat16_rn(wv);
        float hv = __bfloat162float(hb);
        __nv_bfloat16 lb = __float2bfloat16_rn(wv - hv);
        g_Xs[rr*512 + cc] = hb;
        g_Xs[rr*512 + 256 + cc] = lb;
    }
    {
        __nv_bfloat16 mh = __float2bfloat16_rn(1e-6f);
        float mhv = __bfloat162float(mh);
        __nv_bfloat16 ml = __float2bfloat16_rn(1e-6f - mhv);
        __nv_bfloat16 zb = __float2bfloat16_rn(0.0f);
        for (int i = gtid; i < BB*HH; i += NTOT) {
            int rr = i >> 9;
            int cc = i & 511;
            g_zre[i] = 0.0f;
            g_zim[i] = 0.0f;
            g_Are[rr*1024+cc] = zb;
            g_Are[rr*1024+512+cc] = zb;
            g_Aim[rr*1024+cc] = zb;
            g_Aim[rr*1024+512+cc] = zb;
            g_Amod[rr*1024+cc] = mh;
            g_Amod[rr*1024+512+cc] = ml;
        }
    }
    for (int i = gtid; i < HH; i += NTOT) {
        g_bias_re[i] = W_real_b[i] + U_b[i] + b_real[i];
        g_bias_im[i] = W_imag_b[i] + U_b[i] + b_imag[i];
    }
    grid_barrier();

    const __nv_bfloat16* Abase;
    float* C;
    int KP;
    int RSA;
    int WS;
    int WWRAP;
    int ASEG;
    if (which == 0) {
        Abase = g_Are;  C = g_gre;  KP = 1536; RSA = 1024; WS = WSH; WWRAP = 1024; ASEG = 512;
    } else if (which == 1) {
        Abase = g_Aim;  C = g_gim;  KP = 1536; RSA = 1024; WS = WSH; WWRAP = 1024; ASEG = 512;
    } else if (which == 2) {
        Abase = g_Amod; C = g_gtau; KP = 1536; RSA = 1024; WS = WSH; WWRAP = 1024; ASEG = 512;
    } else {
        Abase = g_Xs;   C = g_gux;  KP = 768;  RSA = 512;  WS = WSU; WWRAP = 512;  ASEG = 256;
    }
    int NC = KP >> 7;              // chunks of 128
    int AMASK = WWRAP - 1;         // for kc < WWRAP: ac = kc mod ASEG... use explicit form

    int lr   = tid >> 3;           // 0..63, one loader row per 8 threads
    int lc16 = (tid & 7) * 16;     // 2 consecutive uint4 per thread
    int wid = tid >> 5;            // 0..15
    int wm  = wid & 3;             // 16-row group
    int wn  = wid >> 2;            // 16-col group
    int aFragOff = (wm*16)*ASTR;
    const __nv_bfloat16* sWrow = sW + (wn*16)*WS;

    int oo  = tid & 63;
    int seg = tid >> 6;
    float ob = out_b[oo];

    for (int t = 0; t < TT; t++) {
        // ================= phase A: split-bf16 wmma GEMM ===================
        {
            const __nv_bfloat16* Ag = Abase;
            if (which == 3) {
                Ag = g_Xs + (size_t)t*BB*512;
            }
            const __nv_bfloat16* aRow = Ag + (size_t)(m0+lr)*RSA + lc16;

            wmma::fragment<wmma::accumulator, 16, 16, 16, float> acc;
            wmma::fill_fragment(acc, 0.0f);

            // preload chunk 0 into smem buf0, chunk 1 into register slot B
            uint4 raA0;
            uint4 raA1;
            uint4 raB0;
            uint4 raB1;
            raA0 = *(const uint4*)(aRow);
            raA1 = *(const uint4*)(aRow + 8);
            *(uint4*)(&sA[lr*ASTR + lc16])     = raA0;
            *(uint4*)(&sA[lr*ASTR + lc16 + 8]) = raA1;
            {
                // kc = 128: stacked segments are [Ah | Ah | Al]
                int ac = (128 < WWRAP) ? (128 & (ASEG - 1)) : (128 - ASEG);
                raB0 = *(const uint4*)(aRow + ac);
                raB1 = *(const uint4*)(aRow + ac + 8);
            }
            __syncthreads();

            for (int ch = 0; ch < NC; ch += 2) {
                // even sub-iteration: compute buf0 holding chunk ch
                if (ch + 2 < NC) {
                    int kc = (ch + 2) << 7;
                    int ac = (kc < WWRAP) ? (kc & (ASEG - 1)) : (kc - ASEG);
                    raA0 = *(const uint4*)(aRow + ac);
                    raA1 = *(const uint4*)(aRow + ac + 8);
                }
                {
                    int kc = ch << 7;
                    int wOff = (kc < WWRAP) ? kc : (kc - WWRAP);
                    const __nv_bfloat16* sAc = sA + aFragOff;
                    const __nv_bfloat16* sWc = sWrow + wOff;
                    #pragma unroll
                    for (int q = 0; q < 8; q++) {
                        wmma::fragment<wmma::matrix_a, 16, 16, 16, __nv_bfloat16, wmma::row_major> fa;
                        wmma::fragment<wmma::matrix_b, 16, 16, 16, __nv_bfloat16, wmma::col_major> fb;
                        wmma::load_matrix_sync(fa, sAc + q*16, ASTR);
                        wmma::load_matrix_sync(fb, sWc + q*16, WS);
                        wmma::mma_sync(acc, fa, fb, acc);
                    }
                }
                // slot B holds chunk ch+1 (always valid: NC is even)
                *(uint4*)(&sA[8704 + lr*ASTR + lc16])     = raB0;
                *(uint4*)(&sA[8704 + lr*ASTR + lc16 + 8]) = raB1;
                __syncthreads();

                // odd sub-iteration: compute buf1 holding chunk ch+1
                if (ch + 3 < NC) {
                    int kc = (ch + 3) << 7;
                    int ac = (kc < WWRAP) ? (kc & (ASEG - 1)) : (kc - ASEG);
                    raB0 = *(const uint4*)(aRow + ac);
                    raB1 = *(const uint4*)(aRow + ac + 8);
                }
                {
                    int kc = (ch + 1) << 7;
                    int wOff = (kc < WWRAP) ? kc : (kc - WWRAP);
                    const __nv_bfloat16* sAc = sA + 8704 + aFragOff;
                    const __nv_bfloat16* sWc = sWrow + wOff;
                    #pragma unroll
                    for (int q = 0; q < 8; q++) {
                        wmma::fragment<wmma::matrix_a, 16, 16, 16, __nv_bfloat16, wmma::row_major> fa;
                        wmma::fragment<wmma::matrix_b, 16, 16, 16, __nv_bfloat16, wmma::col_major> fb;
                        wmma::load_matrix_sync(fa, sAc + q*16, ASTR);
                        wmma::load_matrix_sync(fb, sWc + q*16, WS);
                        wmma::mma_sync(acc, fa, fb, acc);
                    }
                }
                if (ch + 2 < NC) {
                    // slot A holds chunk ch+2
                    *(uint4*)(&sA[lr*ASTR + lc16])     = raA0;
                    *(uint4*)(&sA[lr*ASTR + lc16 + 8]) = raA1;
                    __syncthreads();
                }
            }

            float* Cout = C + (size_t)(m0 + wm*16)*512 + n0 + wn*16;
            wmma::store_matrix_sync(Cout, acc, 512, wmma::mem_row_major);
        }

        // ===== deferred readout of step t-1, done by the idle Ux blocks =====
        if (which == 3 && t > 0) {
            int bxu = tile;                  // 0..31 -> B rows [8*bxu, 8*bxu+8)
            float* zst  = (float*)(sW + 64*WSU);   // 8 x 512 floats
            float* redU = zst + 4096;              // seg x row x 64 floats
            __syncthreads();
            const float4* zsrc = (const float4*)(g_zre + (size_t)bxu*8*512);
            for (int i = tid; i < 1024; i += NTHR) {
                ((float4*)zst)[i] = zsrc[i];
            }
            __syncthreads();
            float acc0;
            float acc1;
            float acc2;
            float acc3;
            float acc4;
            float acc5;
            float acc6;
            float acc7;
            acc0 = 0.0f; acc1 = 0.0f; acc2 = 0.0f; acc3 = 0.0f;
            acc4 = 0.0f; acc5 = 0.0f; acc6 = 0.0f; acc7 = 0.0f;
            const float4* wrow = (const float4*)(out_w + (size_t)oo*512 + seg*64);
            #pragma unroll 8
            for (int k4 = 0; k4 < 16; k4++) {
                float4 wv = wrow[k4];
                int zb = seg*64 + k4*4;
                float4 z0 = *(const float4*)(zst + 0*512 + zb);
                float4 z1 = *(const float4*)(zst + 1*512 + zb);
                float4 z2 = *(const float4*)(zst + 2*512 + zb);
                float4 z3 = *(const float4*)(zst + 3*512 + zb);
                acc0 += wv.x*z0.x + wv.y*z0.y + wv.z*z0.z + wv.w*z0.w;
                acc1 += wv.x*z1.x + wv.y*z1.y + wv.z*z1.z + wv.w*z1.w;
                acc2 += wv.x*z2.x + wv.y*z2.y + wv.z*z2.z + wv.w*z2.w;
                acc3 += wv.x*z3.x + wv.y*z3.y + wv.z*z3.z + wv.w*z3.w;
                float4 z4 = *(const float4*)(zst + 4*512 + zb);
                float4 z5 = *(const float4*)(zst + 5*512 + zb);
                float4 z6 = *(const float4*)(zst + 6*512 + zb);
                float4 z7 = *(const float4*)(zst + 7*512 + zb);
                acc4 += wv.x*z4.x + wv.y*z4.y + wv.z*z4.z + wv.w*z4.w;
                acc5 += wv.x*z5.x + wv.y*z5.y + wv.z*z5.z + wv.w*z5.w;
                acc6 += wv.x*z6.x + wv.y*z6.y + wv.z*z6.z + wv.w*z6.w;
                acc7 += wv.x*z7.x + wv.y*z7.y + wv.z*z7.z + wv.w*z7.w;
            }
            redU[(seg*8 + 0)*64 + oo] = acc0;
            redU[(seg*8 + 1)*64 + oo] = acc1;
            redU[(seg*8 + 2)*64 + oo] = acc2;
            redU[(seg*8 + 3)*64 + oo] = acc3;
            redU[(seg*8 + 4)*64 + oo] = acc4;
            redU[(seg*8 + 5)*64 + oo] = acc5;
            redU[(seg*8 + 6)*64 + oo] = acc6;
            redU[(seg*8 + 7)*64 + oo] = acc7;
            __syncthreads();
            if (seg == 0) {
                #pragma unroll
                for (int r = 0; r < 8; r++) {
                    float yv = ob;
                    #pragma unroll
                    for (int s = 0; s < 8; s++) {
                        yv += redU[(s*8 + r)*64 + oo];
                    }
                    y[((size_t)(t-1)*BB + bxu*8 + r)*OUTD + oo] = yv;
                }
            }
        }
        grid_barrier();

        // ========== phase B: elementwise + fused scale sync + update =======
        float dre[2];
        float dimm[2];
        float zreL[2];
        float zimL[2];
        {
            int i2 = bx * 512 + tid;
            float2 vre = ((const float2*)g_gre)[i2];
            float2 vim = ((const float2*)g_gim)[i2];
            float2 vta = ((const float2*)g_gtau)[i2];
            float2 vux = ((const float2*)g_gux)[i2];
            float2 vzr = ((const float2*)g_zre)[i2];
            float2 vzi = ((const float2*)g_zim)[i2];
            int h0 = (i2 & 255) * 2;
            float2 vbr  = *(const float2*)(&g_bias_re[h0]);
            float2 vbi  = *(const float2*)(&g_bias_im[h0]);
            float2 vwtb = *(const float2*)(&W_tau_b[h0]);
            float2 vtb  = *(const float2*)(&tau_bias[h0]);

            float lsum = 0.0f;
            {
                float dzr = vre.x + vux.x + vbr.x - vzr.x;
                float dzi = vim.x + vux.x + vbi.x - vzi.x;
                float tau = clampf(sigf(vta.x + vwtb.x) + vtb.x, 0.01f, 1.0f) + 1e-6f;
                float dr  = clampf(dzr / tau, -10.0f, 10.0f);
                float di  = clampf(dzi / tau, -10.0f, 10.0f);
                lsum += sqrtf(dr*dr + di*di + 1e-12f);
                dre[0] = dr;
                dimm[0] = di;
                zreL[0] = vzr.x;
                zimL[0] = vzi.x;
            }
            {
                float dzr = vre.y + vux.y + vbr.y - vzr.y;
                float dzi = vim.y + vux.y + vbi.y - vzi.y;
                float tau = clampf(sigf(vta.y + vwtb.y) + vtb.y, 0.01f, 1.0f) + 1e-6f;
                float dr  = clampf(dzr / tau, -10.0f, 10.0f);
                float di  = clampf(dzi / tau, -10.0f, 10.0f);
                lsum += sqrtf(dr*dr + di*di + 1e-12f);
                dre[1] = dr;
                dimm[1] = di;
                zreL[1] = vzr.y;
                zimL[1] = vzi.y;
            }
            #pragma unroll
            for (int off = 16; off > 0; off >>= 1) {
                lsum += __shfl_down_sync(0xFFFFFFFFu, lsum, off);
            }
            if ((tid & 31) == 0) {
                rbuf[tid >> 5] = lsum;
            }
            __syncthreads();
            if (tid == 0) {
                float s = 0.0f;
                #pragma unroll
                for (int ww = 0; ww < 16; ww++) {
                    s += rbuf[ww];
                }
                g_partials[bx] = s;
                __threadfence();
                int old = atomicAdd(&g_scnt, 1);
                if (old == (t + 1) * NBLK - 1) {
                    float tot = 0.0f;
                    for (int b = 0; b < NBLK; b++) {
                        tot += ((volatile float*)g_partials)[b];
                    }
                    float mean = tot / (float)(BB * HH);
                    float sc = 1.0f;
                    if (mean > 5.0f) {
                        sc = 5.0f / (mean + 1e-6f);
                    }
                    g_scale = sc;
                    __threadfence();
                    *((volatile int*)&g_sflag) = t + 1;
                }
                while (*((volatile int*)&g_sflag) < t + 1) { }
                s_scale = *((volatile float*)&g_scale);
            }
            __syncthreads();
        }
        {
            float scale = s_scale;

            int i2 = bx * 512 + tid;
            int flat0 = i2 * 2;
            int arw   = flat0 >> 9;
            int acl   = flat0 & 511;
            int abase = arw*1024 + acl;

            float zrA[2];
            float ziA[2];
            #pragma unroll
            for (int j = 0; j < 2; j++) {
                float znr = clampf(zreL[j] + 0.1f * scale * dre[j],  -100.0f, 100.0f);
                float zni = clampf(zimL[j] + 0.1f * scale * dimm[j], -100.0f, 100.0f);
                zrA[j] = znr;
                ziA[j] = zni;
                float arv = tanhf(znr);
                float aiv = tanhf(zni);
                float amv = sqrtf(znr*znr + zni*zni + 1e-12f);
                __nv_bfloat16 hb;
                float hv;
                hb = __float2bfloat16_rn(arv);
                hv = __bfloat162float(hb);
                g_Are[abase+j] = hb;
                g_Are[abase+512+j] = __float2bfloat16_rn(arv - hv);
                hb = __float2bfloat16_rn(aiv);
                hv = __bfloat162float(hb);
                g_Aim[abase+j] = hb;
                g_Aim[abase+512+j] = __float2bfloat16_rn(aiv - hv);
                hb = __float2bfloat16_rn(amv);
                hv = __bfloat162float(hb);
                g_Amod[abase+j] = hb;
                g_Amod[abase+512+j] = __float2bfloat16_rn(amv - hv);
            }
            float2 vout;
            vout.x = zrA[0];
            vout.y = zrA[1];
            ((float2*)g_zre)[i2] = vout;
            float2 vout2;
            vout2.x = ziA[0];
            vout2.y = ziA[1];
            ((float2*)g_zim)[i2] = vout2;
        }
        grid_barrier();
    }

    // ---------------- epilogue: readout of the final step ------------------
    {
        float* zst2 = &zsm[0][0];
        const float4* zsrc = (const float4*)(g_zre + (size_t)bx*1024);
        for (int i = tid; i < 256; i += NTHR) {
            ((float4*)zst2)[i] = zsrc[i];
        }
        __syncthreads();
        float acc0 = 0.0f;
        float acc1 = 0.0f;
        const float4* wrow = (const float4*)(out_w + (size_t)oo*512 + seg*64);
        #pragma unroll 16
        for (int k4 = 0; k4 < 16; k4++) {
            float4 wv = wrow[k4];
            float4 z0 = *(const float4*)(zst2 + seg*64 + k4*4);
            float4 z1 = *(const float4*)(zst2 + 512 + seg*64 + k4*4);
            acc0 += wv.x*z0.x + wv.y*z0.y + wv.z*z0.z + wv.w*z0.w;
            acc1 += wv.x*z1.x + wv.y*z1.y + wv.z*z1.z + wv.w*z1.w;
        }
        red[seg][0][oo] = acc0;
        red[seg][1][oo] = acc1;
        __syncthreads();
        if (seg == 0) {
            #pragma unroll
            for (int r = 0; r < 2; r++) {
                float yv = ob;
                #pragma unroll
                for (int s = 0; s < 8; s++) {
                    yv += red[s][r][oo];
                }
                y[((size_t)(TT-1)*BB + bx*2 + r)*OUTD + oo] = yv;
            }
        }
    }
}

// ---------------- host launcher (graph-capturable, single node) ------------
extern "C" void kernel_launch(void* const* d_in, const int* in_sizes, int n_in,
                              void* d_out, int out_size)
{
    const float* x         = (const float*)d_in[0];
    const float* W_real_w  = (const float*)d_in[1];
    const float* W_real_b  = (const float*)d_in[2];
    const float* W_imag_w  = (const float*)d_in[3];
    const float* W_imag_b  = (const float*)d_in[4];
    const float* U_w       = (const float*)d_in[5];
    const float* U_b       = (const float*)d_in[6];
    const float* W_tau_w   = (const float*)d_in[7];
    const float* W_tau_b   = (const float*)d_in[8];
    const float* mask_real = (const float*)d_in[9];
    const float* mask_imag = (const float*)d_in[10];
    const float* tau_bias  = (const float*)d_in[11];
    const float* b_real    = (const float*)d_in[12];
    const float* b_imag    = (const float*)d_in[13];
    const float* out_w     = (const float*)d_in[14];
    const float* out_b     = (const float*)d_in[15];
    float* y = (float*)d_out;

    // dynamic smem: pinned weight slice (64 x WSH bf16) + A double buffer
    int dyn_smem = (64*WSH + 2*64*ASTR) * (int)sizeof(__nv_bfloat16);
    cudaFuncSetAttribute(twistor_persistent,
                         cudaFuncAttributeMaxDynamicSharedMemorySize, dyn_smem);
    twistor_persistent<<<NBLK, NTHR, dyn_smem>>>(x, W_real_w, W_real_b, W_imag_w, W_imag_b,
                                                 U_w, U_b, W_tau_w, W_tau_b,
                                                 mask_real, mask_imag, tau_bias,
                                                 b_real, b_imag, out_w, out_b, y);
}